// round 2
// baseline (speedup 1.0000x reference)
#include <cuda_runtime.h>
#include <math.h>
#include <stdint.h>

#define H_   16
#define KV_  4
#define D_   128
#define B_   2
#define L_   2048
#define HID  2048
#define M_   (B_*L_)
#define WIN_ 512

// ---------------- scratch (device globals: allocation-guard-safe) ----------------
__device__ float g_qbuf[(size_t)M_*H_*D_];   // raw q proj   [m, 2048]
__device__ float g_kbuf[(size_t)M_*KV_*D_];  // raw k proj   [m, 512]
__device__ float g_vbuf[(size_t)M_*KV_*D_];  // v proj       [m, 512]  (= [B,L,KV,D])
__device__ float g_qt  [(size_t)M_*H_*D_];   // q after norm+rope [B,H,L,D]
__device__ float g_kt  [(size_t)M_*KV_*D_];  // k after norm+rope [B,KV,L,D]
__device__ float g_ao  [(size_t)M_*H_*D_];   // attention out [B,L,H,D]

// ---------------- fp32 GEMM: Y[m,n] = sum_k A[m,k] * W[n,k] ----------------
// Block tile 128x128, K-tile 8, 256 threads, 8x8 register microtile.
__global__ __launch_bounds__(256) void gemm_nt(const float* __restrict__ A,
                                               const float* __restrict__ W,
                                               float* __restrict__ Y,
                                               int M, int N, int K)
{
    __shared__ float As[8][132];
    __shared__ float Ws[8][132];

    const int tid = threadIdx.x;
    const int m0 = blockIdx.y * 128;
    const int n0 = blockIdx.x * 128;

    const int lr = tid >> 1;           // 0..127 row within tile
    const int lc = (tid & 1) * 4;      // 0 or 4

    const float* Ap = A + (size_t)(m0 + lr) * K + lc;
    const float* Wp = W + (size_t)(n0 + lr) * K + lc;

    const int ty = tid >> 4;   // 0..15
    const int tx = tid & 15;   // 0..15

    float acc[8][8];
#pragma unroll
    for (int i = 0; i < 8; i++)
#pragma unroll
        for (int j = 0; j < 8; j++) acc[i][j] = 0.f;

    for (int k0 = 0; k0 < K; k0 += 8) {
        float4 av = *(const float4*)(Ap + k0);
        float4 wv = *(const float4*)(Wp + k0);
        __syncthreads();     // previous iteration's reads done
        As[lc + 0][lr] = av.x; As[lc + 1][lr] = av.y;
        As[lc + 2][lr] = av.z; As[lc + 3][lr] = av.w;
        Ws[lc + 0][lr] = wv.x; Ws[lc + 1][lr] = wv.y;
        Ws[lc + 2][lr] = wv.z; Ws[lc + 3][lr] = wv.w;
        __syncthreads();
#pragma unroll
        for (int kk = 0; kk < 8; kk++) {
            float a[8], b[8];
            *(float4*)(a)     = *(const float4*)&As[kk][ty * 8];
            *(float4*)(a + 4) = *(const float4*)&As[kk][ty * 8 + 4];
            *(float4*)(b)     = *(const float4*)&Ws[kk][tx * 8];
            *(float4*)(b + 4) = *(const float4*)&Ws[kk][tx * 8 + 4];
#pragma unroll
            for (int i = 0; i < 8; i++)
#pragma unroll
                for (int j = 0; j < 8; j++)
                    acc[i][j] = fmaf(a[i], b[j], acc[i][j]);
        }
    }

#pragma unroll
    for (int i = 0; i < 8; i++) {
        float* yp = Y + (size_t)(m0 + ty * 8 + i) * N + n0 + tx * 8;
        *(float4*)(yp)     = make_float4(acc[i][0], acc[i][1], acc[i][2], acc[i][3]);
        *(float4*)(yp + 4) = make_float4(acc[i][4], acc[i][5], acc[i][6], acc[i][7]);
    }
}

// ---------------- QK RMSNorm + RoPE ----------------
// grid (L, B, H+KV), block 128.  hh < H -> q head, else k head.
__global__ __launch_bounds__(128) void norm_rope_kernel(
    const float* __restrict__ qbuf, const float* __restrict__ kbuf,
    const float* __restrict__ cosT, const float* __restrict__ sinT,
    const float* __restrict__ qw,   const float* __restrict__ kw,
    float* __restrict__ qt, float* __restrict__ kt)
{
    const int l  = blockIdx.x;
    const int b  = blockIdx.y;
    const int hh = blockIdx.z;
    const int d  = threadIdx.x;
    const size_t m = (size_t)b * L_ + l;

    float x;
    if (hh < H_) x = qbuf[m * (H_ * D_) + hh * D_ + d];
    else         x = kbuf[m * (KV_ * D_) + (hh - H_) * D_ + d];

    __shared__ float red[4];
    __shared__ float xn[128];

    float v = x * x;
#pragma unroll
    for (int o = 16; o > 0; o >>= 1) v += __shfl_xor_sync(0xffffffffu, v, o);
    if ((d & 31) == 0) red[d >> 5] = v;
    __syncthreads();
    float total = red[0] + red[1] + red[2] + red[3];
    float rms = rsqrtf(total * (1.0f / 128.0f) + 1e-6f);
    float w = (hh < H_) ? qw[d] : kw[d];
    float xv = x * rms * w;
    xn[d] = xv;
    __syncthreads();

    float c = cosT[l * D_ + d];
    float s = sinT[l * D_ + d];
    float rot = (d < 64) ? -xn[d + 64] : xn[d - 64];
    float out = xv * c + rot * s;

    if (hh < H_) qt[(((size_t)(b * H_ + hh)) * L_ + l) * D_ + d] = out;
    else         kt[(((size_t)(b * KV_ + (hh - H_))) * L_ + l) * D_ + d] = out;
}

// ---------------- banded flash attention (fp32) ----------------
// grid (L/64, B*H), block 256.  Tq=64, Tk=64, D=128.
// smem: Qs[64][132] | KVs[64][132] (K then V, same buffer) | S[64][68] | m/l/alpha[64]
#define ATTN_SMEM_FLOATS (2 * 64 * 132 + 64 * 68 + 3 * 64)
#define ATTN_SMEM_BYTES  (ATTN_SMEM_FLOATS * 4)

__global__ __launch_bounds__(256) void attn_kernel(
    const float* __restrict__ qt, const float* __restrict__ kt,
    const float* __restrict__ vb, float* __restrict__ ao)
{
    extern __shared__ float sm[];
    float* Qs   = sm;                    // 64*132
    float* KVs  = sm + 64 * 132;         // 64*132
    float* Ssm  = sm + 2 * 64 * 132;     // 64*68
    float* mrow = Ssm + 64 * 68;
    float* lrow = mrow + 64;
    float* arow = lrow + 64;

    const int tid = threadIdx.x;
    const int qb  = blockIdx.x;
    const int bh  = blockIdx.y;
    const int b   = bh >> 4;     // /H_
    const int h   = bh & 15;
    const int kv  = h >> 2;      // GQA: H/KV = 4
    const int q0  = qb * 64;
    const float scale = 0.08838834764831845f;  // 1/sqrt(128)

    // load Q tile
    const float* qptr = qt + (((size_t)(b * H_ + h)) * L_ + q0) * D_;
    for (int t = tid; t < 64 * 32; t += 256) {
        int r = t >> 5, c = (t & 31) << 2;
        float4 v = *(const float4*)(qptr + r * D_ + c);
        float* dst = Qs + r * 132 + c;
        dst[0] = v.x; dst[1] = v.y; dst[2] = v.z; dst[3] = v.w;
    }
    if (tid < 64) { mrow[tid] = -INFINITY; lrow[tid] = 0.f; }

    float o[8][4];
#pragma unroll
    for (int i = 0; i < 8; i++)
#pragma unroll
        for (int c = 0; c < 4; c++) o[i][c] = 0.f;

    const int r0 = (tid >> 5) * 8;   // PV: 8 rows per thread
    const int c0 = (tid & 31) * 4;   // PV: 4 cols
    const int sy = tid >> 4;         // S: 4 rows
    const int sx = tid & 15;         // S: 4 cols
    __syncthreads();

    int t_lo = qb - 8; if (t_lo < 0) t_lo = 0;
    int t_hi = qb + 8; if (t_hi > (L_ / 64 - 1)) t_hi = L_ / 64 - 1;

    for (int tk = t_lo; tk <= t_hi; tk++) {
        const int j0 = tk * 64;

        // load K tile
        const float* kptr = kt + (((size_t)(b * KV_ + kv)) * L_ + j0) * D_;
        for (int t = tid; t < 64 * 32; t += 256) {
            int r = t >> 5, c = (t & 31) << 2;
            float4 v = *(const float4*)(kptr + r * D_ + c);
            float* dst = KVs + r * 132 + c;
            dst[0] = v.x; dst[1] = v.y; dst[2] = v.z; dst[3] = v.w;
        }
        __syncthreads();

        // S = Q K^T  (4x4 per thread over 64x64)
        float acc[4][4];
#pragma unroll
        for (int i = 0; i < 4; i++)
#pragma unroll
            for (int j = 0; j < 4; j++) acc[i][j] = 0.f;

        for (int d = 0; d < D_; d += 4) {
            float4 a[4], bb[4];
#pragma unroll
            for (int i = 0; i < 4; i++) a[i]  = *(const float4*)(Qs  + (sy * 4 + i) * 132 + d);
#pragma unroll
            for (int j = 0; j < 4; j++) bb[j] = *(const float4*)(KVs + (sx * 4 + j) * 132 + d);
#pragma unroll
            for (int i = 0; i < 4; i++)
#pragma unroll
                for (int j = 0; j < 4; j++) {
                    acc[i][j] = fmaf(a[i].x, bb[j].x, acc[i][j]);
                    acc[i][j] = fmaf(a[i].y, bb[j].y, acc[i][j]);
                    acc[i][j] = fmaf(a[i].z, bb[j].z, acc[i][j]);
                    acc[i][j] = fmaf(a[i].w, bb[j].w, acc[i][j]);
                }
        }

        // mask + scale + store S
#pragma unroll
        for (int i = 0; i < 4; i++) {
            const int ig = q0 + sy * 4 + i;
            float* sp = Ssm + (sy * 4 + i) * 68 + sx * 4;
#pragma unroll
            for (int j = 0; j < 4; j++) {
                const int jg = j0 + sx * 4 + j;
                const int diff = ig - jg;
                const bool valid = (diff <= WIN_) && (diff >= -WIN_);
                sp[j] = valid ? acc[i][j] * scale : -1e30f;
            }
        }
        __syncthreads();

        // online softmax: 4 threads per row
        {
            const int row = tid >> 2;
            const int qq  = tid & 3;
            float* sp = Ssm + row * 68 + qq * 16;
            float lm = -1e38f;
#pragma unroll
            for (int e = 0; e < 16; e++) lm = fmaxf(lm, sp[e]);
            lm = fmaxf(lm, __shfl_xor_sync(0xffffffffu, lm, 1));
            lm = fmaxf(lm, __shfl_xor_sync(0xffffffffu, lm, 2));
            const float m_old = mrow[row];
            const float m_new = fmaxf(m_old, lm);
            float ls = 0.f;
#pragma unroll
            for (int e = 0; e < 16; e++) {
                float p = __expf(sp[e] - m_new);
                sp[e] = p;
                ls += p;
            }
            ls += __shfl_xor_sync(0xffffffffu, ls, 1);
            ls += __shfl_xor_sync(0xffffffffu, ls, 2);
            if (qq == 0) {
                const float al = __expf(m_old - m_new);
                arow[row] = al;
                lrow[row] = al * lrow[row] + ls;
                mrow[row] = m_new;
            }
        }

        // load V tile (overwrites K buffer; K reads finished before prior sync)
        {
            const float* vptr = vb + ((size_t)(b * L_ + j0)) * (KV_ * D_) + kv * D_;
            for (int t = tid; t < 64 * 32; t += 256) {
                int r = t >> 5, c = (t & 31) << 2;
                float4 v = *(const float4*)(vptr + r * (KV_ * D_) + c);
                float* dst = KVs + r * 132 + c;
                dst[0] = v.x; dst[1] = v.y; dst[2] = v.z; dst[3] = v.w;
            }
        }
        __syncthreads();

        // rescale O, then O += P V
#pragma unroll
        for (int i = 0; i < 8; i++) {
            const float al = arow[r0 + i];
#pragma unroll
            for (int c = 0; c < 4; c++) o[i][c] *= al;
        }
        for (int j = 0; j < 64; j++) {
            const float4 v = *(const float4*)(KVs + j * 132 + c0);
            float p[8];
#pragma unroll
            for (int i = 0; i < 8; i++) p[i] = Ssm[(r0 + i) * 68 + j];
#pragma unroll
            for (int i = 0; i < 8; i++) {
                o[i][0] = fmaf(p[i], v.x, o[i][0]);
                o[i][1] = fmaf(p[i], v.y, o[i][1]);
                o[i][2] = fmaf(p[i], v.z, o[i][2]);
                o[i][3] = fmaf(p[i], v.w, o[i][3]);
            }
        }
        __syncthreads();
    }

    // epilogue: divide by l, write [B, L, H, D]
#pragma unroll
    for (int i = 0; i < 8; i++) {
        const float inv = 1.0f / lrow[r0 + i];
        float* op = ao + (((size_t)(b * L_ + q0 + r0 + i)) * H_ + h) * D_ + c0;
        *(float4*)op = make_float4(o[i][0] * inv, o[i][1] * inv,
                                   o[i][2] * inv, o[i][3] * inv);
    }
}

// ---------------- launch ----------------
extern "C" void kernel_launch(void* const* d_in, const int* in_sizes, int n_in,
                              void* d_out, int out_size)
{
    const float* x    = (const float*)d_in[0];
    const float* cosT = (const float*)d_in[1];
    const float* sinT = (const float*)d_in[2];
    const float* Wq   = (const float*)d_in[3];
    const float* Wk   = (const float*)d_in[4];
    const float* Wv   = (const float*)d_in[5];
    const float* Wo   = (const float*)d_in[6];
    const float* qw   = (const float*)d_in[7];
    const float* kw   = (const float*)d_in[8];
    float* out = (float*)d_out;

    float *qbuf, *kbuf, *vbuf, *qt, *kt, *ao;
    cudaGetSymbolAddress((void**)&qbuf, g_qbuf);
    cudaGetSymbolAddress((void**)&kbuf, g_kbuf);
    cudaGetSymbolAddress((void**)&vbuf, g_vbuf);
    cudaGetSymbolAddress((void**)&qt,   g_qt);
    cudaGetSymbolAddress((void**)&kt,   g_kt);
    cudaGetSymbolAddress((void**)&ao,   g_ao);

    // QKV projections
    gemm_nt<<<dim3(HID / 128, M_ / 128), 256>>>(x, Wq, qbuf, M_, HID, HID);
    gemm_nt<<<dim3((KV_ * D_) / 128, M_ / 128), 256>>>(x, Wk, kbuf, M_, KV_ * D_, HID);
    gemm_nt<<<dim3((KV_ * D_) / 128, M_ / 128), 256>>>(x, Wv, vbuf, M_, KV_ * D_, HID);

    // RMSNorm + RoPE
    norm_rope_kernel<<<dim3(L_, B_, H_ + KV_), 128>>>(qbuf, kbuf, cosT, sinT, qw, kw, qt, kt);

    // banded flash attention
    cudaFuncSetAttribute(attn_kernel, cudaFuncAttributeMaxDynamicSharedMemorySize, ATTN_SMEM_BYTES);
    attn_kernel<<<dim3(L_ / 64, B_ * H_), 256, ATTN_SMEM_BYTES>>>(qt, kt, vbuf, ao);

    // output projection -> d_out
    gemm_nt<<<dim3(HID / 128, M_ / 128), 256>>>(ao, Wo, out, M_, HID, HID);
}

// round 4
// speedup vs baseline: 1.5018x; 1.5018x over previous
#include <cuda_runtime.h>
#include <cuda_bf16.h>
#include <math.h>
#include <stdint.h>

#define H_   16
#define KV_  4
#define D_   128
#define B_   2
#define L_   2048
#define HID  2048
#define M_   (B_*L_)
#define WIN_ 512
#define K3   (3*HID)     // 6144: split-expanded K
#define NQKV 3072        // 2048 q + 512 k + 512 v

// ---------------- scratch (device globals: allocation-guard-safe) ----------------
__device__ __align__(16) __nv_bfloat16 g_x3   [(size_t)M_  * K3];   // x split-expanded
__device__ __align__(16) __nv_bfloat16 g_wqkv3[(size_t)NQKV * K3];  // fused QKV weights
__device__ __align__(16) __nv_bfloat16 g_wo3  [(size_t)HID * K3];   // Wo split-expanded
__device__ __align__(16) __nv_bfloat16 g_ao3  [(size_t)M_  * K3];   // attn out split-expanded
__device__ __align__(16) float g_qkvbuf[(size_t)M_ * NQKV];         // raw qkv proj [m, 3072]
__device__ __align__(16) float g_qt [(size_t)M_*H_*D_];             // q normed+rope [B,H,L,D]
__device__ __align__(16) float g_kt [(size_t)M_*KV_*D_];            // k normed+rope [B,KV,L,D]
__device__ __align__(16) float g_ao [(size_t)M_*H_*D_];             // attn out [B,L,H,D]

// ---------------- fp32 -> split-bf16 conversion ----------------
// mode 0 (A-type): [hi | lo | hi]   mode 1 (B-type): [hi | hi | lo]
__global__ __launch_bounds__(256) void convert_split(
    const float* __restrict__ src, __nv_bfloat16* __restrict__ dst,
    int Kf, int total, int mode)
{
    int i = (blockIdx.x * 256 + threadIdx.x) * 4;
    if (i >= total) return;
    float4 v = *(const float4*)(src + i);
    int r = i / Kf;
    int k = i - r * Kf;
    size_t base = (size_t)r * (3 * Kf) + k;

    float f[4] = {v.x, v.y, v.z, v.w};
    __nv_bfloat16 hi[4], lo[4];
#pragma unroll
    for (int e = 0; e < 4; e++) {
        hi[e] = __float2bfloat16_rn(f[e]);
        lo[e] = __float2bfloat16_rn(f[e] - __bfloat162float(hi[e]));
    }
    __nv_bfloat162* d0 = (__nv_bfloat162*)(dst + base);
    __nv_bfloat162* d1 = (__nv_bfloat162*)(dst + base + Kf);
    __nv_bfloat162* d2 = (__nv_bfloat162*)(dst + base + 2 * Kf);
    __nv_bfloat162 hp0 = {hi[0], hi[1]}, hp1 = {hi[2], hi[3]};
    __nv_bfloat162 lp0 = {lo[0], lo[1]}, lp1 = {lo[2], lo[3]};
    d0[0] = hp0; d0[1] = hp1;
    if (mode == 0) {
        d1[0] = lp0; d1[1] = lp1;
        d2[0] = hp0; d2[1] = hp1;
    } else {
        d1[0] = hp0; d1[1] = hp1;
        d2[0] = lp0; d2[1] = lp1;
    }
}

// ---------------- bf16 tensor-core GEMM: C[m,n] = sum_k A[m,k]*B[n,k] ----------------
// 128x128 tile, BK=32 bf16, 256 threads (8 warps, 2x4), m16n8k16 mma.
__global__ __launch_bounds__(256, 2) void gemm_mma_nt(
    const __nv_bfloat16* __restrict__ A,   // [M, K] row-major
    const __nv_bfloat16* __restrict__ B,   // [N, K] row-major
    float* __restrict__ C, int M, int N, int K)
{
    // row stride 40 elems (80B) -> conflict-free ldmatrix & STS
    __shared__ __nv_bfloat16 As[128 * 40];
    __shared__ __nv_bfloat16 Bs[128 * 40];

    const int tid  = threadIdx.x;
    const int m0   = blockIdx.y * 128;
    const int n0   = blockIdx.x * 128;
    const int lrow = tid >> 2;          // 0..63
    const int lch  = tid & 3;           // 16B chunk in row
    const int wid  = tid >> 5;
    const int lane = tid & 31;
    const int wm   = wid & 1;           // warp row (64 rows each)
    const int wn   = wid >> 1;          // warp col (32 cols each)

    float acc[4][4][4];
#pragma unroll
    for (int i = 0; i < 4; i++)
#pragma unroll
        for (int j = 0; j < 4; j++)
#pragma unroll
            for (int r = 0; r < 4; r++) acc[i][j][r] = 0.f;

    const uint32_t as_base = (uint32_t)__cvta_generic_to_shared(As);
    const uint32_t bs_base = (uint32_t)__cvta_generic_to_shared(Bs);

    const __nv_bfloat16* Ap = A + (size_t)(m0 + lrow) * K + lch * 8;
    const __nv_bfloat16* Bp = B + (size_t)(n0 + lrow) * K + lch * 8;
    const size_t half = (size_t)64 * K;

    for (int k0 = 0; k0 < K; k0 += 32) {
        uint4 av0 = *(const uint4*)(Ap + k0);
        uint4 av1 = *(const uint4*)(Ap + k0 + half);
        uint4 bv0 = *(const uint4*)(Bp + k0);
        uint4 bv1 = *(const uint4*)(Bp + k0 + half);
        __syncthreads();
        *(uint4*)(As + lrow * 40 + lch * 8)        = av0;
        *(uint4*)(As + (lrow + 64) * 40 + lch * 8) = av1;
        *(uint4*)(Bs + lrow * 40 + lch * 8)        = bv0;
        *(uint4*)(Bs + (lrow + 64) * 40 + lch * 8) = bv1;
        __syncthreads();

#pragma unroll
        for (int ks = 0; ks < 2; ks++) {
            uint32_t afr[4][4];
            uint32_t bfr[4][2];
#pragma unroll
            for (int mi = 0; mi < 4; mi++) {
                int row = wm * 64 + mi * 16 + (lane & 15);
                uint32_t addr = as_base + row * 80 + ks * 32 + ((lane >> 4) << 4);
                asm volatile(
                    "ldmatrix.sync.aligned.m8n8.x4.shared.b16 {%0,%1,%2,%3}, [%4];"
                    : "=r"(afr[mi][0]), "=r"(afr[mi][1]),
                      "=r"(afr[mi][2]), "=r"(afr[mi][3])
                    : "r"(addr));
            }
#pragma unroll
            for (int ni = 0; ni < 4; ni++) {
                int row = wn * 32 + ni * 8 + (lane & 7);
                uint32_t addr = bs_base + row * 80 + ks * 32 + (((lane >> 3) & 1) << 4);
                asm volatile(
                    "ldmatrix.sync.aligned.m8n8.x2.shared.b16 {%0,%1}, [%2];"
                    : "=r"(bfr[ni][0]), "=r"(bfr[ni][1])
                    : "r"(addr));
            }
#pragma unroll
            for (int mi = 0; mi < 4; mi++)
#pragma unroll
                for (int ni = 0; ni < 4; ni++) {
                    asm volatile(
                        "mma.sync.aligned.m16n8k16.row.col.f32.bf16.bf16.f32 "
                        "{%0,%1,%2,%3}, {%4,%5,%6,%7}, {%8,%9}, {%0,%1,%2,%3};"
                        : "+f"(acc[mi][ni][0]), "+f"(acc[mi][ni][1]),
                          "+f"(acc[mi][ni][2]), "+f"(acc[mi][ni][3])
                        : "r"(afr[mi][0]), "r"(afr[mi][1]),
                          "r"(afr[mi][2]), "r"(afr[mi][3]),
                          "r"(bfr[ni][0]), "r"(bfr[ni][1]));
                }
        }
    }

    const int tr = lane >> 2;
    const int tc = (lane & 3) * 2;
#pragma unroll
    for (int mi = 0; mi < 4; mi++)
#pragma unroll
        for (int ni = 0; ni < 4; ni++) {
            int row = m0 + wm * 64 + mi * 16 + tr;
            int col = n0 + wn * 32 + ni * 8 + tc;
            *(float2*)(C + (size_t)row * N + col) =
                make_float2(acc[mi][ni][0], acc[mi][ni][1]);
            *(float2*)(C + (size_t)(row + 8) * N + col) =
                make_float2(acc[mi][ni][2], acc[mi][ni][3]);
        }
}

// ---------------- QK RMSNorm + RoPE (reads fused qkv buffer) ----------------
__global__ __launch_bounds__(128) void norm_rope_kernel(
    const float* __restrict__ qkv,
    const float* __restrict__ cosT, const float* __restrict__ sinT,
    const float* __restrict__ qw,   const float* __restrict__ kw,
    float* __restrict__ qt, float* __restrict__ kt)
{
    const int l  = blockIdx.x;
    const int b  = blockIdx.y;
    const int hh = blockIdx.z;
    const int d  = threadIdx.x;
    const size_t m = (size_t)b * L_ + l;

    float x;
    if (hh < H_) x = qkv[m * NQKV + hh * D_ + d];
    else         x = qkv[m * NQKV + HID + (hh - H_) * D_ + d];

    __shared__ float red[4];
    __shared__ float xn[128];

    float v = x * x;
#pragma unroll
    for (int o = 16; o > 0; o >>= 1) v += __shfl_xor_sync(0xffffffffu, v, o);
    if ((d & 31) == 0) red[d >> 5] = v;
    __syncthreads();
    float total = red[0] + red[1] + red[2] + red[3];
    float rms = rsqrtf(total * (1.0f / 128.0f) + 1e-6f);
    float w = (hh < H_) ? qw[d] : kw[d];
    float xv = x * rms * w;
    xn[d] = xv;
    __syncthreads();

    float c = cosT[l * D_ + d];
    float s = sinT[l * D_ + d];
    float rot = (d < 64) ? -xn[d + 64] : xn[d - 64];
    float out = xv * c + rot * s;

    if (hh < H_) qt[(((size_t)(b * H_ + hh)) * L_ + l) * D_ + d] = out;
    else         kt[(((size_t)(b * KV_ + (hh - H_))) * L_ + l) * D_ + d] = out;
}

// ---------------- banded flash attention (fp32) ----------------
#define ATTN_SMEM_FLOATS (2 * 64 * 132 + 64 * 68 + 3 * 64)
#define ATTN_SMEM_BYTES  (ATTN_SMEM_FLOATS * 4)

__global__ __launch_bounds__(256) void attn_kernel(
    const float* __restrict__ qt, const float* __restrict__ kt,
    const float* __restrict__ qkv, float* __restrict__ ao)
{
    extern __shared__ float sm[];
    float* Qs   = sm;
    float* KVs  = sm + 64 * 132;
    float* Ssm  = sm + 2 * 64 * 132;
    float* mrow = Ssm + 64 * 68;
    float* lrow = mrow + 64;
    float* arow = lrow + 64;

    const int tid = threadIdx.x;
    const int qb  = blockIdx.x;
    const int bh  = blockIdx.y;
    const int b   = bh >> 4;
    const int h   = bh & 15;
    const int kv  = h >> 2;
    const int q0  = qb * 64;
    const float scale = 0.08838834764831845f;

    const float* qptr = qt + (((size_t)(b * H_ + h)) * L_ + q0) * D_;
    for (int t = tid; t < 64 * 32; t += 256) {
        int r = t >> 5, c = (t & 31) << 2;
        float4 v = *(const float4*)(qptr + r * D_ + c);
        float* dst = Qs + r * 132 + c;
        dst[0] = v.x; dst[1] = v.y; dst[2] = v.z; dst[3] = v.w;
    }
    if (tid < 64) { mrow[tid] = -INFINITY; lrow[tid] = 0.f; }

    float o[8][4];
#pragma unroll
    for (int i = 0; i < 8; i++)
#pragma unroll
        for (int c = 0; c < 4; c++) o[i][c] = 0.f;

    const int r0 = (tid >> 5) * 8;
    const int c0 = (tid & 31) * 4;
    const int sy = tid >> 4;
    const int sx = tid & 15;
    __syncthreads();

    int t_lo = qb - 8; if (t_lo < 0) t_lo = 0;
    int t_hi = qb + 8; if (t_hi > (L_ / 64 - 1)) t_hi = L_ / 64 - 1;

    for (int tk = t_lo; tk <= t_hi; tk++) {
        const int j0 = tk * 64;

        const float* kptr = kt + (((size_t)(b * KV_ + kv)) * L_ + j0) * D_;
        for (int t = tid; t < 64 * 32; t += 256) {
            int r = t >> 5, c = (t & 31) << 2;
            float4 v = *(const float4*)(kptr + r * D_ + c);
            float* dst = KVs + r * 132 + c;
            dst[0] = v.x; dst[1] = v.y; dst[2] = v.z; dst[3] = v.w;
        }
        __syncthreads();

        float acc[4][4];
#pragma unroll
        for (int i = 0; i < 4; i++)
#pragma unroll
            for (int j = 0; j < 4; j++) acc[i][j] = 0.f;

        for (int d = 0; d < D_; d += 4) {
            float4 a[4], bb[4];
#pragma unroll
            for (int i = 0; i < 4; i++) a[i]  = *(const float4*)(Qs  + (sy * 4 + i) * 132 + d);
#pragma unroll
            for (int j = 0; j < 4; j++) bb[j] = *(const float4*)(KVs + (sx * 4 + j) * 132 + d);
#pragma unroll
            for (int i = 0; i < 4; i++)
#pragma unroll
                for (int j = 0; j < 4; j++) {
                    acc[i][j] = fmaf(a[i].x, bb[j].x, acc[i][j]);
                    acc[i][j] = fmaf(a[i].y, bb[j].y, acc[i][j]);
                    acc[i][j] = fmaf(a[i].z, bb[j].z, acc[i][j]);
                    acc[i][j] = fmaf(a[i].w, bb[j].w, acc[i][j]);
                }
        }

#pragma unroll
        for (int i = 0; i < 4; i++) {
            const int ig = q0 + sy * 4 + i;
            float* sp = Ssm + (sy * 4 + i) * 68 + sx * 4;
#pragma unroll
            for (int j = 0; j < 4; j++) {
                const int jg = j0 + sx * 4 + j;
                const int diff = ig - jg;
                const bool valid = (diff <= WIN_) && (diff >= -WIN_);
                sp[j] = valid ? acc[i][j] * scale : -1e30f;
            }
        }
        __syncthreads();

        {
            const int row = tid >> 2;
            const int qq  = tid & 3;
            float* sp = Ssm + row * 68 + qq * 16;
            float lm = -1e38f;
#pragma unroll
            for (int e = 0; e < 16; e++) lm = fmaxf(lm, sp[e]);
            lm = fmaxf(lm, __shfl_xor_sync(0xffffffffu, lm, 1));
            lm = fmaxf(lm, __shfl_xor_sync(0xffffffffu, lm, 2));
            const float m_old = mrow[row];
            const float m_new = fmaxf(m_old, lm);
            float ls = 0.f;
#pragma unroll
            for (int e = 0; e < 16; e++) {
                float p = __expf(sp[e] - m_new);
                sp[e] = p;
                ls += p;
            }
            ls += __shfl_xor_sync(0xffffffffu, ls, 1);
            ls += __shfl_xor_sync(0xffffffffu, ls, 2);
            if (qq == 0) {
                const float al = __expf(m_old - m_new);
                arow[row] = al;
                lrow[row] = al * lrow[row] + ls;
                mrow[row] = m_new;
            }
        }

        {
            const float* vptr = qkv + ((size_t)(b * L_ + j0)) * NQKV + HID + KV_ * D_ + kv * D_;
            for (int t = tid; t < 64 * 32; t += 256) {
                int r = t >> 5, c = (t & 31) << 2;
                float4 v = *(const float4*)(vptr + r * NQKV + c);
                float* dst = KVs + r * 132 + c;
                dst[0] = v.x; dst[1] = v.y; dst[2] = v.z; dst[3] = v.w;
            }
        }
        __syncthreads();

#pragma unroll
        for (int i = 0; i < 8; i++) {
            const float al = arow[r0 + i];
#pragma unroll
            for (int c = 0; c < 4; c++) o[i][c] *= al;
        }
        for (int j = 0; j < 64; j++) {
            const float4 v = *(const float4*)(KVs + j * 132 + c0);
            float p[8];
#pragma unroll
            for (int i = 0; i < 8; i++) p[i] = Ssm[(r0 + i) * 68 + j];
#pragma unroll
            for (int i = 0; i < 8; i++) {
                o[i][0] = fmaf(p[i], v.x, o[i][0]);
                o[i][1] = fmaf(p[i], v.y, o[i][1]);
                o[i][2] = fmaf(p[i], v.z, o[i][2]);
                o[i][3] = fmaf(p[i], v.w, o[i][3]);
            }
        }
        __syncthreads();
    }

#pragma unroll
    for (int i = 0; i < 8; i++) {
        const float inv = 1.0f / lrow[r0 + i];
        float* op = ao + (((size_t)(b * L_ + q0 + r0 + i)) * H_ + h) * D_ + c0;
        *(float4*)op = make_float4(o[i][0] * inv, o[i][1] * inv,
                                   o[i][2] * inv, o[i][3] * inv);
    }
}

// ---------------- launch ----------------
extern "C" void kernel_launch(void* const* d_in, const int* in_sizes, int n_in,
                              void* d_out, int out_size)
{
    const float* x    = (const float*)d_in[0];
    const float* cosT = (const float*)d_in[1];
    const float* sinT = (const float*)d_in[2];
    const float* Wq   = (const float*)d_in[3];
    const float* Wk   = (const float*)d_in[4];
    const float* Wv   = (const float*)d_in[5];
    const float* Wo   = (const float*)d_in[6];
    const float* qw   = (const float*)d_in[7];
    const float* kw   = (const float*)d_in[8];
    float* out = (float*)d_out;

    __nv_bfloat16 *x3, *wqkv3, *wo3, *ao3;
    float *qkvbuf, *qt, *kt, *ao;
    cudaGetSymbolAddress((void**)&x3,     g_x3);
    cudaGetSymbolAddress((void**)&wqkv3,  g_wqkv3);
    cudaGetSymbolAddress((void**)&wo3,    g_wo3);
    cudaGetSymbolAddress((void**)&ao3,    g_ao3);
    cudaGetSymbolAddress((void**)&qkvbuf, g_qkvbuf);
    cudaGetSymbolAddress((void**)&qt,     g_qt);
    cudaGetSymbolAddress((void**)&kt,     g_kt);
    cudaGetSymbolAddress((void**)&ao,     g_ao);

    // split-bf16 conversions
    {
        int tot = M_ * HID;                 // x: A-type
        convert_split<<<tot / 1024, 256>>>(x, x3, HID, tot, 0);
        tot = HID * HID;                    // Wq: B-type -> rows [0,2048)
        convert_split<<<tot / 1024, 256>>>(Wq, wqkv3, HID, tot, 1);
        tot = KV_ * D_ * HID;               // Wk -> rows [2048,2560)
        convert_split<<<tot / 1024, 256>>>(Wk, wqkv3 + (size_t)HID * K3, HID, tot, 1);
        convert_split<<<tot / 1024, 256>>>(Wv, wqkv3 + (size_t)(HID + KV_ * D_) * K3, HID, tot, 1);
        tot = HID * HID;                    // Wo: B-type
        convert_split<<<tot / 1024, 256>>>(Wo, wo3, HID, tot, 1);
    }

    // fused QKV projection: [4096, 3072]
    gemm_mma_nt<<<dim3(NQKV / 128, M_ / 128), 256>>>(x3, wqkv3, qkvbuf, M_, NQKV, K3);

    // RMSNorm + RoPE
    norm_rope_kernel<<<dim3(L_, B_, H_ + KV_), 128>>>(qkvbuf, cosT, sinT, qw, kw, qt, kt);

    // banded flash attention (V read straight from qkvbuf)
    cudaFuncSetAttribute(attn_kernel, cudaFuncAttributeMaxDynamicSharedMemorySize, ATTN_SMEM_BYTES);
    attn_kernel<<<dim3(L_ / 64, B_ * H_), 256, ATTN_SMEM_BYTES>>>(qt, kt, qkvbuf, ao);

    // attention output -> split bf16 -> O projection
    {
        int tot = M_ * HID;
        convert_split<<<tot / 1024, 256>>>(ao, ao3, HID, tot, 0);
    }
    gemm_mma_nt<<<dim3(HID / 128, M_ / 128), 256>>>(ao3, wo3, out, M_, HID, K3);
}

// round 5
// speedup vs baseline: 2.4526x; 1.6331x over previous
#include <cuda_runtime.h>
#include <cuda_bf16.h>
#include <math.h>
#include <stdint.h>

#define H_   16
#define KV_  4
#define D_   128
#define B_   2
#define L_   2048
#define HID  2048
#define M_   (B_*L_)
#define WIN_ 512
#define K3   (3*HID)
#define NQKV 3072

// ---------------- scratch ----------------
__device__ __align__(16) __nv_bfloat16 g_x3   [(size_t)M_  * K3];
__device__ __align__(16) __nv_bfloat16 g_wqkv3[(size_t)NQKV * K3];
__device__ __align__(16) __nv_bfloat16 g_wo3  [(size_t)HID * K3];
__device__ __align__(16) __nv_bfloat16 g_ao3  [(size_t)M_  * K3];
__device__ __align__(16) float g_qkvbuf[(size_t)M_ * NQKV];
__device__ __align__(16) __nv_bfloat16 g_qh [(size_t)B_*H_*L_*D_];
__device__ __align__(16) __nv_bfloat16 g_ql [(size_t)B_*H_*L_*D_];
__device__ __align__(16) __nv_bfloat16 g_kh [(size_t)B_*KV_*L_*D_];
__device__ __align__(16) __nv_bfloat16 g_kl [(size_t)B_*KV_*L_*D_];
__device__ __align__(16) __nv_bfloat16 g_vth[(size_t)B_*KV_*D_*L_];  // [b][kv][d][l]
__device__ __align__(16) __nv_bfloat16 g_vtl[(size_t)B_*KV_*D_*L_];

// ---------------- fp32 -> split-bf16 conversion ----------------
// mode 0 (A-type): [hi | lo | hi]   mode 1 (B-type): [hi | hi | lo]
__global__ __launch_bounds__(256) void convert_split(
    const float* __restrict__ src, __nv_bfloat16* __restrict__ dst,
    int Kf, int total, int mode)
{
    int i = (blockIdx.x * 256 + threadIdx.x) * 4;
    if (i >= total) return;
    float4 v = *(const float4*)(src + i);
    int r = i / Kf;
    int k = i - r * Kf;
    size_t base = (size_t)r * (3 * Kf) + k;

    float f[4] = {v.x, v.y, v.z, v.w};
    __nv_bfloat16 hi[4], lo[4];
#pragma unroll
    for (int e = 0; e < 4; e++) {
        hi[e] = __float2bfloat16_rn(f[e]);
        lo[e] = __float2bfloat16_rn(f[e] - __bfloat162float(hi[e]));
    }
    __nv_bfloat162* d0 = (__nv_bfloat162*)(dst + base);
    __nv_bfloat162* d1 = (__nv_bfloat162*)(dst + base + Kf);
    __nv_bfloat162* d2 = (__nv_bfloat162*)(dst + base + 2 * Kf);
    __nv_bfloat162 hp0 = {hi[0], hi[1]}, hp1 = {hi[2], hi[3]};
    __nv_bfloat162 lp0 = {lo[0], lo[1]}, lp1 = {lo[2], lo[3]};
    d0[0] = hp0; d0[1] = hp1;
    if (mode == 0) { d1[0] = lp0; d1[1] = lp1; d2[0] = hp0; d2[1] = hp1; }
    else          { d1[0] = hp0; d1[1] = hp1; d2[0] = lp0; d2[1] = lp1; }
}

// ---------------- bf16 tensor-core GEMM (unchanged from R3) ----------------
__global__ __launch_bounds__(256, 2) void gemm_mma_nt(
    const __nv_bfloat16* __restrict__ A,
    const __nv_bfloat16* __restrict__ B,
    float* __restrict__ C, int M, int N, int K)
{
    __shared__ __nv_bfloat16 As[128 * 40];
    __shared__ __nv_bfloat16 Bs[128 * 40];

    const int tid  = threadIdx.x;
    const int m0   = blockIdx.y * 128;
    const int n0   = blockIdx.x * 128;
    const int lrow = tid >> 2;
    const int lch  = tid & 3;
    const int wid  = tid >> 5;
    const int lane = tid & 31;
    const int wm   = wid & 1;
    const int wn   = wid >> 1;

    float acc[4][4][4];
#pragma unroll
    for (int i = 0; i < 4; i++)
#pragma unroll
        for (int j = 0; j < 4; j++)
#pragma unroll
            for (int r = 0; r < 4; r++) acc[i][j][r] = 0.f;

    const uint32_t as_base = (uint32_t)__cvta_generic_to_shared(As);
    const uint32_t bs_base = (uint32_t)__cvta_generic_to_shared(Bs);

    const __nv_bfloat16* Ap = A + (size_t)(m0 + lrow) * K + lch * 8;
    const __nv_bfloat16* Bp = B + (size_t)(n0 + lrow) * K + lch * 8;
    const size_t half = (size_t)64 * K;

    for (int k0 = 0; k0 < K; k0 += 32) {
        uint4 av0 = *(const uint4*)(Ap + k0);
        uint4 av1 = *(const uint4*)(Ap + k0 + half);
        uint4 bv0 = *(const uint4*)(Bp + k0);
        uint4 bv1 = *(const uint4*)(Bp + k0 + half);
        __syncthreads();
        *(uint4*)(As + lrow * 40 + lch * 8)        = av0;
        *(uint4*)(As + (lrow + 64) * 40 + lch * 8) = av1;
        *(uint4*)(Bs + lrow * 40 + lch * 8)        = bv0;
        *(uint4*)(Bs + (lrow + 64) * 40 + lch * 8) = bv1;
        __syncthreads();

#pragma unroll
        for (int ks = 0; ks < 2; ks++) {
            uint32_t afr[4][4];
            uint32_t bfr[4][2];
#pragma unroll
            for (int mi = 0; mi < 4; mi++) {
                int row = wm * 64 + mi * 16 + (lane & 15);
                uint32_t addr = as_base + row * 80 + ks * 32 + ((lane >> 4) << 4);
                asm volatile(
                    "ldmatrix.sync.aligned.m8n8.x4.shared.b16 {%0,%1,%2,%3}, [%4];"
                    : "=r"(afr[mi][0]), "=r"(afr[mi][1]),
                      "=r"(afr[mi][2]), "=r"(afr[mi][3])
                    : "r"(addr));
            }
#pragma unroll
            for (int ni = 0; ni < 4; ni++) {
                int row = wn * 32 + ni * 8 + (lane & 7);
                uint32_t addr = bs_base + row * 80 + ks * 32 + (((lane >> 3) & 1) << 4);
                asm volatile(
                    "ldmatrix.sync.aligned.m8n8.x2.shared.b16 {%0,%1}, [%2];"
                    : "=r"(bfr[ni][0]), "=r"(bfr[ni][1])
                    : "r"(addr));
            }
#pragma unroll
            for (int mi = 0; mi < 4; mi++)
#pragma unroll
                for (int ni = 0; ni < 4; ni++) {
                    asm volatile(
                        "mma.sync.aligned.m16n8k16.row.col.f32.bf16.bf16.f32 "
                        "{%0,%1,%2,%3}, {%4,%5,%6,%7}, {%8,%9}, {%0,%1,%2,%3};"
                        : "+f"(acc[mi][ni][0]), "+f"(acc[mi][ni][1]),
                          "+f"(acc[mi][ni][2]), "+f"(acc[mi][ni][3])
                        : "r"(afr[mi][0]), "r"(afr[mi][1]),
                          "r"(afr[mi][2]), "r"(afr[mi][3]),
                          "r"(bfr[ni][0]), "r"(bfr[ni][1]));
                }
        }
    }

    const int tr = lane >> 2;
    const int tc = (lane & 3) * 2;
#pragma unroll
    for (int mi = 0; mi < 4; mi++)
#pragma unroll
        for (int ni = 0; ni < 4; ni++) {
            int row = m0 + wm * 64 + mi * 16 + tr;
            int col = n0 + wn * 32 + ni * 8 + tc;
            *(float2*)(C + (size_t)row * N + col) =
                make_float2(acc[mi][ni][0], acc[mi][ni][1]);
            *(float2*)(C + (size_t)(row + 8) * N + col) =
                make_float2(acc[mi][ni][2], acc[mi][ni][3]);
        }
}

// ---------------- QK RMSNorm + RoPE + split-bf16 output (+ V split/transpose) ----------------
// grid (L, B, H+2*KV), block 128
__global__ __launch_bounds__(128) void norm_rope_split(
    const float* __restrict__ qkv,
    const float* __restrict__ cosT, const float* __restrict__ sinT,
    const float* __restrict__ qw,   const float* __restrict__ kw,
    __nv_bfloat16* __restrict__ qh, __nv_bfloat16* __restrict__ ql,
    __nv_bfloat16* __restrict__ kh, __nv_bfloat16* __restrict__ kl,
    __nv_bfloat16* __restrict__ vth, __nv_bfloat16* __restrict__ vtl)
{
    const int l  = blockIdx.x;
    const int b  = blockIdx.y;
    const int hh = blockIdx.z;
    const int d  = threadIdx.x;
    const size_t m = (size_t)b * L_ + l;

    if (hh >= H_ + KV_) {             // V path: split + transpose
        const int kv = hh - (H_ + KV_);
        float x = qkv[m * NQKV + HID + KV_ * D_ + kv * D_ + d];
        __nv_bfloat16 hi = __float2bfloat16_rn(x);
        __nv_bfloat16 lo = __float2bfloat16_rn(x - __bfloat162float(hi));
        size_t idx = ((size_t)(b * KV_ + kv) * D_ + d) * L_ + l;
        vth[idx] = hi; vtl[idx] = lo;
        return;
    }

    float x;
    if (hh < H_) x = qkv[m * NQKV + hh * D_ + d];
    else         x = qkv[m * NQKV + HID + (hh - H_) * D_ + d];

    __shared__ float red[4];
    __shared__ float xn[128];

    float v = x * x;
#pragma unroll
    for (int o = 16; o > 0; o >>= 1) v += __shfl_xor_sync(0xffffffffu, v, o);
    if ((d & 31) == 0) red[d >> 5] = v;
    __syncthreads();
    float total = red[0] + red[1] + red[2] + red[3];
    float rms = rsqrtf(total * (1.0f / 128.0f) + 1e-6f);
    float w = (hh < H_) ? qw[d] : kw[d];
    float xv = x * rms * w;
    xn[d] = xv;
    __syncthreads();

    float c = cosT[l * D_ + d];
    float s = sinT[l * D_ + d];
    float rot = (d < 64) ? -xn[d + 64] : xn[d - 64];
    float out = xv * c + rot * s;

    __nv_bfloat16 hi = __float2bfloat16_rn(out);
    __nv_bfloat16 lo = __float2bfloat16_rn(out - __bfloat162float(hi));
    if (hh < H_) {
        size_t idx = (((size_t)(b * H_ + hh)) * L_ + l) * D_ + d;
        qh[idx] = hi; ql[idx] = lo;
    } else {
        size_t idx = (((size_t)(b * KV_ + (hh - H_))) * L_ + l) * D_ + d;
        kh[idx] = hi; kl[idx] = lo;
    }
}

// ---------------- tensor-core banded flash attention ----------------
// Tq=128, Tk=64, 256 threads (8 warps, 16 rows each). Split-bf16 3-term mma
// for both S and PV. Writes split-expanded ao3 [m][hi|lo|hi] directly.
#define SQH 0
#define SQL 17408
#define SKH 34816
#define SKL 43520
#define SVH 52224
#define SVL 61440
#define ATTN_SMEM_ELEMS 70656
#define ATTN_SMEM_BYTES (ATTN_SMEM_ELEMS * 2)

#define LDSM_X4(r0,r1,r2,r3,addr) \
    asm volatile("ldmatrix.sync.aligned.m8n8.x4.shared.b16 {%0,%1,%2,%3}, [%4];" \
        : "=r"(r0),"=r"(r1),"=r"(r2),"=r"(r3) : "r"(addr))
#define MMA16816(c,a0,a1,a2,a3,b0,b1) \
    asm volatile("mma.sync.aligned.m16n8k16.row.col.f32.bf16.bf16.f32 " \
        "{%0,%1,%2,%3},{%4,%5,%6,%7},{%8,%9},{%0,%1,%2,%3};" \
        : "+f"((c)[0]),"+f"((c)[1]),"+f"((c)[2]),"+f"((c)[3]) \
        : "r"(a0),"r"(a1),"r"(a2),"r"(a3),"r"(b0),"r"(b1))

__device__ __forceinline__ uint32_t pkhi(float x, float y) {
    __nv_bfloat162 t = __floats2bfloat162_rn(x, y);
    return *reinterpret_cast<uint32_t*>(&t);
}
__device__ __forceinline__ uint32_t pklo(float x, float y) {
    __nv_bfloat16 hx = __float2bfloat16_rn(x), hy = __float2bfloat16_rn(y);
    __nv_bfloat162 t = __floats2bfloat162_rn(x - __bfloat162float(hx),
                                             y - __bfloat162float(hy));
    return *reinterpret_cast<uint32_t*>(&t);
}

__global__ __launch_bounds__(256) void attn_mma_kernel(
    const __nv_bfloat16* __restrict__ qhg, const __nv_bfloat16* __restrict__ qlg,
    const __nv_bfloat16* __restrict__ khg, const __nv_bfloat16* __restrict__ klg,
    const __nv_bfloat16* __restrict__ vhg, const __nv_bfloat16* __restrict__ vlg,
    __nv_bfloat16* __restrict__ ao3)
{
    extern __shared__ __nv_bfloat16 sm[];
    __nv_bfloat16* Qh  = sm + SQH;
    __nv_bfloat16* Ql  = sm + SQL;
    __nv_bfloat16* Kh  = sm + SKH;
    __nv_bfloat16* Kl  = sm + SKL;
    __nv_bfloat16* Vth = sm + SVH;
    __nv_bfloat16* Vtl = sm + SVL;

    const int tid  = threadIdx.x;
    const int wid  = tid >> 5;
    const int lane = tid & 31;
    const int qb   = blockIdx.x;
    const int bh   = blockIdx.y;
    const int b    = bh >> 4;
    const int h    = bh & 15;
    const int kv   = h >> 2;
    const int q0   = qb * 128;
    const float scale = 0.08838834764831845f;

    // ---- load Q tile (hi+lo) ----
    {
        const __nv_bfloat16* ph = qhg + (((size_t)(b * H_ + h)) * L_ + q0) * D_;
        const __nv_bfloat16* pl = qlg + (((size_t)(b * H_ + h)) * L_ + q0) * D_;
        for (int t = tid; t < 128 * 16; t += 256) {
            int r = t >> 4, c = (t & 15) * 8;
            *(uint4*)(Qh + r * 136 + c) = *(const uint4*)(ph + r * 128 + c);
            *(uint4*)(Ql + r * 136 + c) = *(const uint4*)(pl + r * 128 + c);
        }
    }

    float o[16][4];
#pragma unroll
    for (int n = 0; n < 16; n++)
#pragma unroll
        for (int e = 0; e < 4; e++) o[n][e] = 0.f;
    float mrow[2] = {-1e30f, -1e30f};
    float lrow[2] = {0.f, 0.f};

    const int i1 = q0 + wid * 16 + (lane >> 2);   // global q row 1
    const int i2 = i1 + 8;

    int t_lo = (q0 - WIN_) >> 6; if (t_lo < 0) t_lo = 0;
    int t_hi = (q0 + 127 + WIN_) >> 6; if (t_hi > L_ / 64 - 1) t_hi = L_ / 64 - 1;

    const uint32_t qh_b = (uint32_t)__cvta_generic_to_shared(Qh);
    const uint32_t ql_b = (uint32_t)__cvta_generic_to_shared(Ql);
    const uint32_t kh_b = (uint32_t)__cvta_generic_to_shared(Kh);
    const uint32_t kl_b = (uint32_t)__cvta_generic_to_shared(Kl);
    const uint32_t vh_b = (uint32_t)__cvta_generic_to_shared(Vth);
    const uint32_t vl_b = (uint32_t)__cvta_generic_to_shared(Vtl);

    for (int tk = t_lo; tk <= t_hi; tk++) {
        const int j0 = tk * 64;

        // ---- load K tile (hi+lo) and V^T tile (hi+lo) ----
        {
            const __nv_bfloat16* ph = khg + (((size_t)(b * KV_ + kv)) * L_ + j0) * D_;
            const __nv_bfloat16* pl = klg + (((size_t)(b * KV_ + kv)) * L_ + j0) * D_;
            for (int t = tid; t < 64 * 16; t += 256) {
                int r = t >> 4, c = (t & 15) * 8;
                *(uint4*)(Kh + r * 136 + c) = *(const uint4*)(ph + r * 128 + c);
                *(uint4*)(Kl + r * 136 + c) = *(const uint4*)(pl + r * 128 + c);
            }
            const __nv_bfloat16* vh = vhg + ((size_t)(b * KV_ + kv) * D_) * L_ + j0;
            const __nv_bfloat16* vl = vlg + ((size_t)(b * KV_ + kv) * D_) * L_ + j0;
            for (int t = tid; t < 128 * 8; t += 256) {
                int d = t >> 3, c = (t & 7) * 8;
                *(uint4*)(Vth + d * 72 + c) = *(const uint4*)(vh + (size_t)d * L_ + c);
                *(uint4*)(Vtl + d * 72 + c) = *(const uint4*)(vl + (size_t)d * L_ + c);
            }
        }
        __syncthreads();

        // ---- S = Qh*Kh + Ql*Kh + Qh*Kl ----
        float s[8][4];
#pragma unroll
        for (int n = 0; n < 8; n++)
#pragma unroll
            for (int e = 0; e < 4; e++) s[n][e] = 0.f;

#pragma unroll
        for (int pass = 0; pass < 3; pass++) {
            const uint32_t ab = (pass == 1) ? ql_b : qh_b;
            const uint32_t bb = (pass == 2) ? kl_b : kh_b;
#pragma unroll
            for (int k8 = 0; k8 < 8; k8++) {
                uint32_t a0, a1, a2, a3;
                uint32_t aaddr = ab + ((wid * 16 + (lane & 15)) * 136
                                       + k8 * 16 + ((lane >> 4) * 8)) * 2;
                LDSM_X4(a0, a1, a2, a3, aaddr);
#pragma unroll
                for (int n2 = 0; n2 < 4; n2++) {
                    uint32_t b0, b1, b2, b3;
                    uint32_t baddr = bb + ((n2 * 16 + (lane & 15)) * 136
                                           + k8 * 16 + ((lane >> 4) * 8)) * 2;
                    LDSM_X4(b0, b1, b2, b3, baddr);
                    MMA16816(s[2 * n2],     a0, a1, a2, a3, b0, b2);
                    MMA16816(s[2 * n2 + 1], a0, a1, a2, a3, b1, b3);
                }
            }
        }

        // ---- mask + scale ----
#pragma unroll
        for (int n = 0; n < 8; n++) {
            const int jc = j0 + n * 8 + (lane & 3) * 2;
#pragma unroll
            for (int e = 0; e < 4; e++) {
                const int i = (e < 2) ? i1 : i2;
                const int j = jc + (e & 1);
                const bool valid = (unsigned)(i - j + WIN_) <= (unsigned)(2 * WIN_);
                s[n][e] = valid ? s[n][e] * scale : -1e30f;
            }
        }

        // ---- online softmax (warp-local, 2 rows/thread) ----
        float m1 = -1e30f, m2 = -1e30f;
#pragma unroll
        for (int n = 0; n < 8; n++) {
            m1 = fmaxf(m1, fmaxf(s[n][0], s[n][1]));
            m2 = fmaxf(m2, fmaxf(s[n][2], s[n][3]));
        }
        m1 = fmaxf(m1, __shfl_xor_sync(0xffffffffu, m1, 1));
        m1 = fmaxf(m1, __shfl_xor_sync(0xffffffffu, m1, 2));
        m2 = fmaxf(m2, __shfl_xor_sync(0xffffffffu, m2, 1));
        m2 = fmaxf(m2, __shfl_xor_sync(0xffffffffu, m2, 2));
        const float mn1 = fmaxf(mrow[0], m1);
        const float mn2 = fmaxf(mrow[1], m2);
        const float al1 = __expf(mrow[0] - mn1);
        const float al2 = __expf(mrow[1] - mn2);
        float ls1 = 0.f, ls2 = 0.f;
#pragma unroll
        for (int n = 0; n < 8; n++) {
            s[n][0] = __expf(s[n][0] - mn1);
            s[n][1] = __expf(s[n][1] - mn1);
            s[n][2] = __expf(s[n][2] - mn2);
            s[n][3] = __expf(s[n][3] - mn2);
            ls1 += s[n][0] + s[n][1];
            ls2 += s[n][2] + s[n][3];
        }
        ls1 += __shfl_xor_sync(0xffffffffu, ls1, 1);
        ls1 += __shfl_xor_sync(0xffffffffu, ls1, 2);
        ls2 += __shfl_xor_sync(0xffffffffu, ls2, 1);
        ls2 += __shfl_xor_sync(0xffffffffu, ls2, 2);
        lrow[0] = al1 * lrow[0] + ls1;
        lrow[1] = al2 * lrow[1] + ls2;
        mrow[0] = mn1;
        mrow[1] = mn2;
#pragma unroll
        for (int n = 0; n < 16; n++) {
            o[n][0] *= al1; o[n][1] *= al1;
            o[n][2] *= al2; o[n][3] *= al2;
        }

        // ---- O += Ph*Vh + Pl*Vh + Ph*Vl (P from registers) ----
#pragma unroll
        for (int kk = 0; kk < 4; kk++) {
            const int t0 = 2 * kk, t1 = 2 * kk + 1;
            uint32_t ah[4], al[4];
            ah[0] = pkhi(s[t0][0], s[t0][1]); ah[1] = pkhi(s[t0][2], s[t0][3]);
            ah[2] = pkhi(s[t1][0], s[t1][1]); ah[3] = pkhi(s[t1][2], s[t1][3]);
            al[0] = pklo(s[t0][0], s[t0][1]); al[1] = pklo(s[t0][2], s[t0][3]);
            al[2] = pklo(s[t1][0], s[t1][1]); al[3] = pklo(s[t1][2], s[t1][3]);
#pragma unroll
            for (int n2 = 0; n2 < 8; n2++) {
                uint32_t h0, h1, h2, h3, l0, l1, l2, l3;
                uint32_t va = ((n2 * 16 + (lane & 15)) * 72
                               + kk * 16 + ((lane >> 4) * 8)) * 2;
                LDSM_X4(h0, h1, h2, h3, vh_b + va);
                LDSM_X4(l0, l1, l2, l3, vl_b + va);
                MMA16816(o[2 * n2], ah[0], ah[1], ah[2], ah[3], h0, h2);
                MMA16816(o[2 * n2], al[0], al[1], al[2], al[3], h0, h2);
                MMA16816(o[2 * n2], ah[0], ah[1], ah[2], ah[3], l0, l2);
                MMA16816(o[2 * n2 + 1], ah[0], ah[1], ah[2], ah[3], h1, h3);
                MMA16816(o[2 * n2 + 1], al[0], al[1], al[2], al[3], h1, h3);
                MMA16816(o[2 * n2 + 1], ah[0], ah[1], ah[2], ah[3], l1, l3);
            }
        }
        __syncthreads();
    }

    // ---- epilogue: /l, write split-expanded ao3 ----
    const float inv1 = 1.0f / lrow[0];
    const float inv2 = 1.0f / lrow[1];
    const size_t m1r = (size_t)b * L_ + i1;   // i1 = q0 + local row
    const size_t m2r = (size_t)b * L_ + i2;
#pragma unroll
    for (int n = 0; n < 16; n++) {
        const int col = h * 128 + n * 8 + (lane & 3) * 2;
        {
            float v0 = o[n][0] * inv1, v1 = o[n][1] * inv1;
            __nv_bfloat16 h0 = __float2bfloat16_rn(v0), h1v = __float2bfloat16_rn(v1);
            __nv_bfloat162 hp = {h0, h1v};
            __nv_bfloat162 lp = {__float2bfloat16_rn(v0 - __bfloat162float(h0)),
                                 __float2bfloat16_rn(v1 - __bfloat162float(h1v))};
            *(__nv_bfloat162*)(ao3 + m1r * K3 + col)        = hp;
            *(__nv_bfloat162*)(ao3 + m1r * K3 + HID + col)  = lp;
            *(__nv_bfloat162*)(ao3 + m1r * K3 + 2*HID + col) = hp;
        }
        {
            float v0 = o[n][2] * inv2, v1 = o[n][3] * inv2;
            __nv_bfloat16 h0 = __float2bfloat16_rn(v0), h1v = __float2bfloat16_rn(v1);
            __nv_bfloat162 hp = {h0, h1v};
            __nv_bfloat162 lp = {__float2bfloat16_rn(v0 - __bfloat162float(h0)),
                                 __float2bfloat16_rn(v1 - __bfloat162float(h1v))};
            *(__nv_bfloat162*)(ao3 + m2r * K3 + col)        = hp;
            *(__nv_bfloat162*)(ao3 + m2r * K3 + HID + col)  = lp;
            *(__nv_bfloat162*)(ao3 + m2r * K3 + 2*HID + col) = hp;
        }
    }
}

// ---------------- launch ----------------
extern "C" void kernel_launch(void* const* d_in, const int* in_sizes, int n_in,
                              void* d_out, int out_size)
{
    const float* x    = (const float*)d_in[0];
    const float* cosT = (const float*)d_in[1];
    const float* sinT = (const float*)d_in[2];
    const float* Wq   = (const float*)d_in[3];
    const float* Wk   = (const float*)d_in[4];
    const float* Wv   = (const float*)d_in[5];
    const float* Wo   = (const float*)d_in[6];
    const float* qw   = (const float*)d_in[7];
    const float* kw   = (const float*)d_in[8];
    float* out = (float*)d_out;

    __nv_bfloat16 *x3, *wqkv3, *wo3, *ao3, *qh, *ql, *kh, *kl, *vth, *vtl;
    float *qkvbuf;
    cudaGetSymbolAddress((void**)&x3,     g_x3);
    cudaGetSymbolAddress((void**)&wqkv3,  g_wqkv3);
    cudaGetSymbolAddress((void**)&wo3,    g_wo3);
    cudaGetSymbolAddress((void**)&ao3,    g_ao3);
    cudaGetSymbolAddress((void**)&qkvbuf, g_qkvbuf);
    cudaGetSymbolAddress((void**)&qh,     g_qh);
    cudaGetSymbolAddress((void**)&ql,     g_ql);
    cudaGetSymbolAddress((void**)&kh,     g_kh);
    cudaGetSymbolAddress((void**)&kl,     g_kl);
    cudaGetSymbolAddress((void**)&vth,    g_vth);
    cudaGetSymbolAddress((void**)&vtl,    g_vtl);

    // split-bf16 conversions
    {
        int tot = M_ * HID;
        convert_split<<<tot / 1024, 256>>>(x, x3, HID, tot, 0);
        tot = HID * HID;
        convert_split<<<tot / 1024, 256>>>(Wq, wqkv3, HID, tot, 1);
        tot = KV_ * D_ * HID;
        convert_split<<<tot / 1024, 256>>>(Wk, wqkv3 + (size_t)HID * K3, HID, tot, 1);
        convert_split<<<tot / 1024, 256>>>(Wv, wqkv3 + (size_t)(HID + KV_ * D_) * K3, HID, tot, 1);
        tot = HID * HID;
        convert_split<<<tot / 1024, 256>>>(Wo, wo3, HID, tot, 1);
    }

    // fused QKV projection
    gemm_mma_nt<<<dim3(NQKV / 128, M_ / 128), 256>>>(x3, wqkv3, qkvbuf, M_, NQKV, K3);

    // RMSNorm + RoPE + split outputs (+ V split/transpose)
    norm_rope_split<<<dim3(L_, B_, H_ + 2 * KV_), 128>>>(
        qkvbuf, cosT, sinT, qw, kw, qh, ql, kh, kl, vth, vtl);

    // tensor-core banded flash attention -> ao3 (split-expanded)
    cudaFuncSetAttribute(attn_mma_kernel,
                         cudaFuncAttributeMaxDynamicSharedMemorySize, ATTN_SMEM_BYTES);
    attn_mma_kernel<<<dim3(L_ / 128, B_ * H_), 256, ATTN_SMEM_BYTES>>>(
        qh, ql, kh, kl, vth, vtl, ao3);

    // output projection
    gemm_mma_nt<<<dim3(HID / 128, M_ / 128), 256>>>(ao3, wo3, out, M_, HID, K3);
}

// round 7
// speedup vs baseline: 2.8653x; 1.1683x over previous
#include <cuda_runtime.h>
#include <cuda_bf16.h>
#include <math.h>
#include <stdint.h>

#define H_   16
#define KV_  4
#define D_   128
#define B_   2
#define L_   2048
#define HID  2048
#define M_   (B_*L_)
#define WIN_ 512
#define K3   (3*HID)
#define NQKV 3072

// ---------------- scratch ----------------
__device__ __align__(16) __nv_bfloat16 g_x3   [(size_t)M_  * K3];
__device__ __align__(16) __nv_bfloat16 g_wqkv3[(size_t)NQKV * K3];
__device__ __align__(16) __nv_bfloat16 g_wo3  [(size_t)HID * K3];
__device__ __align__(16) __nv_bfloat16 g_ao3  [(size_t)M_  * K3];
__device__ __align__(16) float g_qkvbuf[(size_t)M_ * NQKV];
__device__ __align__(16) __nv_bfloat16 g_qh [(size_t)B_*H_*L_*D_];
__device__ __align__(16) __nv_bfloat16 g_ql [(size_t)B_*H_*L_*D_];
__device__ __align__(16) __nv_bfloat16 g_kh [(size_t)B_*KV_*L_*D_];
__device__ __align__(16) __nv_bfloat16 g_kl [(size_t)B_*KV_*L_*D_];
__device__ __align__(16) __nv_bfloat16 g_vth[(size_t)B_*KV_*D_*L_];
__device__ __align__(16) __nv_bfloat16 g_vtl[(size_t)B_*KV_*D_*L_];

#define CP_ASYNC16(dst, src) \
    asm volatile("cp.async.cg.shared.global [%0], [%1], 16;" :: "r"(dst), "l"(src))
#define CP_COMMIT() asm volatile("cp.async.commit_group;")
#define CP_WAIT(n)  asm volatile("cp.async.wait_group %0;" :: "n"(n))

// ---------------- fp32 -> split-bf16 conversion ----------------
__global__ __launch_bounds__(256) void convert_split(
    const float* __restrict__ src, __nv_bfloat16* __restrict__ dst,
    int Kf, int total, int mode)
{
    int i = (blockIdx.x * 256 + threadIdx.x) * 4;
    if (i >= total) return;
    float4 v = *(const float4*)(src + i);
    int r = i / Kf;
    int k = i - r * Kf;
    size_t base = (size_t)r * (3 * Kf) + k;

    float f[4] = {v.x, v.y, v.z, v.w};
    __nv_bfloat16 hi[4], lo[4];
#pragma unroll
    for (int e = 0; e < 4; e++) {
        hi[e] = __float2bfloat16_rn(f[e]);
        lo[e] = __float2bfloat16_rn(f[e] - __bfloat162float(hi[e]));
    }
    __nv_bfloat162* d0 = (__nv_bfloat162*)(dst + base);
    __nv_bfloat162* d1 = (__nv_bfloat162*)(dst + base + Kf);
    __nv_bfloat162* d2 = (__nv_bfloat162*)(dst + base + 2 * Kf);
    __nv_bfloat162 hp0 = {hi[0], hi[1]}, hp1 = {hi[2], hi[3]};
    __nv_bfloat162 lp0 = {lo[0], lo[1]}, lp1 = {lo[2], lo[3]};
    d0[0] = hp0; d0[1] = hp1;
    if (mode == 0) { d1[0] = lp0; d1[1] = lp1; d2[0] = hp0; d2[1] = hp1; }
    else          { d1[0] = hp0; d1[1] = hp1; d2[0] = lp0; d2[1] = lp1; }
}

// ---------------- pipelined bf16 tensor-core GEMM ----------------
// 128x128 tile, BK=32, 4-stage cp.async pipeline, 256 threads.
#define GSTAGE 4
#define GA_ELEMS (128 * 40)
#define GSTAGE_BYTES (2 * GA_ELEMS * 2)       // A+B per stage, bytes
#define GSMEM_BYTES (GSTAGE * GSTAGE_BYTES)   // 81920

__global__ __launch_bounds__(256, 2) void gemm_mma_nt(
    const __nv_bfloat16* __restrict__ A,
    const __nv_bfloat16* __restrict__ B,
    float* __restrict__ C, int M, int N, int K)
{
    extern __shared__ __nv_bfloat16 gsm[];

    const int tid  = threadIdx.x;
    const int m0   = blockIdx.y * 128;
    const int n0   = blockIdx.x * 128;
    const int lrow = tid >> 2;
    const int lch  = tid & 3;
    const int wid  = tid >> 5;
    const int lane = tid & 31;
    const int wm   = wid & 1;
    const int wn   = wid >> 1;

    float acc[4][4][4];
#pragma unroll
    for (int i = 0; i < 4; i++)
#pragma unroll
        for (int j = 0; j < 4; j++)
#pragma unroll
            for (int r = 0; r < 4; r++) acc[i][j][r] = 0.f;

    const uint32_t sbase = (uint32_t)__cvta_generic_to_shared(gsm);
    const __nv_bfloat16* Ap = A + (size_t)(m0 + lrow) * K + lch * 8;
    const __nv_bfloat16* Bp = B + (size_t)(n0 + lrow) * K + lch * 8;
    const size_t half = (size_t)64 * K;

    const uint32_t doff = (lrow * 40 + lch * 8) * 2;   // byte offset within tile

    auto load_stage = [&](int s, int k0) {
        uint32_t sa = sbase + s * GSTAGE_BYTES;
        uint32_t sb = sa + GA_ELEMS * 2;
        CP_ASYNC16(sa + doff,               Ap + k0);
        CP_ASYNC16(sa + doff + 64 * 80,     Ap + k0 + half);
        CP_ASYNC16(sb + doff,               Bp + k0);
        CP_ASYNC16(sb + doff + 64 * 80,     Bp + k0 + half);
    };

    int k_next = 0;
#pragma unroll
    for (int s = 0; s < GSTAGE - 1; s++) {
        load_stage(s, k_next); k_next += 32;
        CP_COMMIT();
    }

    const int kt_total = K / 32;
    for (int kt = 0; kt < kt_total; kt++) {
        CP_WAIT(GSTAGE - 2);
        __syncthreads();
        if (k_next < K) { load_stage((kt + GSTAGE - 1) & (GSTAGE - 1), k_next); k_next += 32; }
        CP_COMMIT();

        const uint32_t as_base = sbase + (kt & (GSTAGE - 1)) * GSTAGE_BYTES;
        const uint32_t bs_base = as_base + GA_ELEMS * 2;

#pragma unroll
        for (int ks = 0; ks < 2; ks++) {
            uint32_t afr[4][4];
            uint32_t bfr[4][2];
#pragma unroll
            for (int mi = 0; mi < 4; mi++) {
                int row = wm * 64 + mi * 16 + (lane & 15);
                uint32_t addr = as_base + row * 80 + ks * 32 + ((lane >> 4) << 4);
                asm volatile(
                    "ldmatrix.sync.aligned.m8n8.x4.shared.b16 {%0,%1,%2,%3}, [%4];"
                    : "=r"(afr[mi][0]), "=r"(afr[mi][1]),
                      "=r"(afr[mi][2]), "=r"(afr[mi][3])
                    : "r"(addr));
            }
#pragma unroll
            for (int ni = 0; ni < 4; ni++) {
                int row = wn * 32 + ni * 8 + (lane & 7);
                uint32_t addr = bs_base + row * 80 + ks * 32 + (((lane >> 3) & 1) << 4);
                asm volatile(
                    "ldmatrix.sync.aligned.m8n8.x2.shared.b16 {%0,%1}, [%2];"
                    : "=r"(bfr[ni][0]), "=r"(bfr[ni][1])
                    : "r"(addr));
            }
#pragma unroll
            for (int mi = 0; mi < 4; mi++)
#pragma unroll
                for (int ni = 0; ni < 4; ni++) {
                    asm volatile(
                        "mma.sync.aligned.m16n8k16.row.col.f32.bf16.bf16.f32 "
                        "{%0,%1,%2,%3}, {%4,%5,%6,%7}, {%8,%9}, {%0,%1,%2,%3};"
                        : "+f"(acc[mi][ni][0]), "+f"(acc[mi][ni][1]),
                          "+f"(acc[mi][ni][2]), "+f"(acc[mi][ni][3])
                        : "r"(afr[mi][0]), "r"(afr[mi][1]),
                          "r"(afr[mi][2]), "r"(afr[mi][3]),
                          "r"(bfr[ni][0]), "r"(bfr[ni][1]));
                }
        }
    }

    const int tr = lane >> 2;
    const int tc = (lane & 3) * 2;
#pragma unroll
    for (int mi = 0; mi < 4; mi++)
#pragma unroll
        for (int ni = 0; ni < 4; ni++) {
            int row = m0 + wm * 64 + mi * 16 + tr;
            int col = n0 + wn * 32 + ni * 8 + tc;
            *(float2*)(C + (size_t)row * N + col) =
                make_float2(acc[mi][ni][0], acc[mi][ni][1]);
            *(float2*)(C + (size_t)(row + 8) * N + col) =
                make_float2(acc[mi][ni][2], acc[mi][ni][3]);
        }
}

// ---------------- QK RMSNorm + RoPE + split outputs (+ V split/transpose) ----------------
__global__ __launch_bounds__(128) void norm_rope_split(
    const float* __restrict__ qkv,
    const float* __restrict__ cosT, const float* __restrict__ sinT,
    const float* __restrict__ qw,   const float* __restrict__ kw,
    __nv_bfloat16* __restrict__ qh, __nv_bfloat16* __restrict__ ql,
    __nv_bfloat16* __restrict__ kh, __nv_bfloat16* __restrict__ kl,
    __nv_bfloat16* __restrict__ vth, __nv_bfloat16* __restrict__ vtl)
{
    const int l  = blockIdx.x;
    const int b  = blockIdx.y;
    const int hh = blockIdx.z;
    const int d  = threadIdx.x;
    const size_t m = (size_t)b * L_ + l;

    if (hh >= H_ + KV_) {
        const int kv = hh - (H_ + KV_);
        float x = qkv[m * NQKV + HID + KV_ * D_ + kv * D_ + d];
        __nv_bfloat16 hi = __float2bfloat16_rn(x);
        __nv_bfloat16 lo = __float2bfloat16_rn(x - __bfloat162float(hi));
        size_t idx = ((size_t)(b * KV_ + kv) * D_ + d) * L_ + l;
        vth[idx] = hi; vtl[idx] = lo;
        return;
    }

    float x;
    if (hh < H_) x = qkv[m * NQKV + hh * D_ + d];
    else         x = qkv[m * NQKV + HID + (hh - H_) * D_ + d];

    __shared__ float red[4];
    __shared__ float xn[128];

    float v = x * x;
#pragma unroll
    for (int o = 16; o > 0; o >>= 1) v += __shfl_xor_sync(0xffffffffu, v, o);
    if ((d & 31) == 0) red[d >> 5] = v;
    __syncthreads();
    float total = red[0] + red[1] + red[2] + red[3];
    float rms = rsqrtf(total * (1.0f / 128.0f) + 1e-6f);
    float w = (hh < H_) ? qw[d] : kw[d];
    float xv = x * rms * w;
    xn[d] = xv;
    __syncthreads();

    float c = cosT[l * D_ + d];
    float s = sinT[l * D_ + d];
    float rot = (d < 64) ? -xn[d + 64] : xn[d - 64];
    float out = xv * c + rot * s;

    __nv_bfloat16 hi = __float2bfloat16_rn(out);
    __nv_bfloat16 lo = __float2bfloat16_rn(out - __bfloat162float(hi));
    if (hh < H_) {
        size_t idx = (((size_t)(b * H_ + hh)) * L_ + l) * D_ + d;
        qh[idx] = hi; ql[idx] = lo;
    } else {
        size_t idx = (((size_t)(b * KV_ + (hh - H_))) * L_ + l) * D_ + d;
        kh[idx] = hi; kl[idx] = lo;
    }
}

// ---------------- tensor-core banded flash attention, double-buffered KV ----------------
// Layout (elems): Qh 0..17408 | Ql 17408.. | stage s at 34816 + s*35840:
//   Kh +0 (8704) | Kl +8704 | Vth +17408 (9216) | Vtl +26624
#define AQH 0
#define AQL 17408
#define AKV0 34816
#define AKVSTR 35840
#define ATTN_SMEM_ELEMS (AKV0 + 2 * AKVSTR)
#define ATTN_SMEM_BYTES (ATTN_SMEM_ELEMS * 2)   // 212992

#define LDSM_X4(r0,r1,r2,r3,addr) \
    asm volatile("ldmatrix.sync.aligned.m8n8.x4.shared.b16 {%0,%1,%2,%3}, [%4];" \
        : "=r"(r0),"=r"(r1),"=r"(r2),"=r"(r3) : "r"(addr))
#define MMA16816(c,a0,a1,a2,a3,b0,b1) \
    asm volatile("mma.sync.aligned.m16n8k16.row.col.f32.bf16.bf16.f32 " \
        "{%0,%1,%2,%3},{%4,%5,%6,%7},{%8,%9},{%0,%1,%2,%3};" \
        : "+f"((c)[0]),"+f"((c)[1]),"+f"((c)[2]),"+f"((c)[3]) \
        : "r"(a0),"r"(a1),"r"(a2),"r"(a3),"r"(b0),"r"(b1))

__device__ __forceinline__ uint32_t pkhi(float x, float y) {
    __nv_bfloat162 t = __floats2bfloat162_rn(x, y);
    return *reinterpret_cast<uint32_t*>(&t);
}
__device__ __forceinline__ uint32_t pklo(float x, float y) {
    __nv_bfloat16 hx = __float2bfloat16_rn(x), hy = __float2bfloat16_rn(y);
    __nv_bfloat162 t = __floats2bfloat162_rn(x - __bfloat162float(hx),
                                             y - __bfloat162float(hy));
    return *reinterpret_cast<uint32_t*>(&t);
}

__global__ __launch_bounds__(256) void attn_mma_kernel(
    const __nv_bfloat16* __restrict__ qhg, const __nv_bfloat16* __restrict__ qlg,
    const __nv_bfloat16* __restrict__ khg, const __nv_bfloat16* __restrict__ klg,
    const __nv_bfloat16* __restrict__ vhg, const __nv_bfloat16* __restrict__ vlg,
    __nv_bfloat16* __restrict__ ao3)
{
    extern __shared__ __nv_bfloat16 sm[];

    const int tid  = threadIdx.x;
    const int wid  = tid >> 5;
    const int lane = tid & 31;
    const int qb   = blockIdx.x;
    const int bh   = blockIdx.y;
    const int b    = bh >> 4;
    const int h    = bh & 15;
    const int kv   = h >> 2;
    const int q0   = qb * 128;
    const float scale = 0.08838834764831845f;

    const uint32_t smb  = (uint32_t)__cvta_generic_to_shared(sm);
    const uint32_t qh_b = smb + AQH * 2;
    const uint32_t ql_b = smb + AQL * 2;

    const __nv_bfloat16* kh_src = khg + ((size_t)(b * KV_ + kv)) * L_ * D_;
    const __nv_bfloat16* kl_src = klg + ((size_t)(b * KV_ + kv)) * L_ * D_;
    const __nv_bfloat16* vh_src = vhg + ((size_t)(b * KV_ + kv) * D_) * L_;
    const __nv_bfloat16* vl_src = vlg + ((size_t)(b * KV_ + kv) * D_) * L_;

    auto load_kv = [&](int st, int tk) {
        const int j0 = tk * 64;
        const uint32_t kvb  = smb + (AKV0 + st * AKVSTR) * 2;
        const uint32_t khb  = kvb;
        const uint32_t klb  = kvb + 8704 * 2;
        const uint32_t vhb  = kvb + 17408 * 2;
        const uint32_t vlb  = kvb + 26624 * 2;
#pragma unroll
        for (int t = tid; t < 64 * 16; t += 256) {
            int r = t >> 4, c = (t & 15) * 8;
            uint32_t so = (r * 136 + c) * 2;
            size_t go = (size_t)(j0 + r) * D_ + c;
            CP_ASYNC16(khb + so, kh_src + go);
            CP_ASYNC16(klb + so, kl_src + go);
        }
#pragma unroll
        for (int t = tid; t < 128 * 8; t += 256) {
            int d = t >> 3, c = (t & 7) * 8;
            uint32_t so = (d * 72 + c) * 2;
            size_t go = (size_t)d * L_ + j0 + c;
            CP_ASYNC16(vhb + so, vh_src + go);
            CP_ASYNC16(vlb + so, vl_src + go);
        }
    };

    // ---- load Q tile (hi+lo), plain stores ----
    {
        const __nv_bfloat16* ph = qhg + (((size_t)(b * H_ + h)) * L_ + q0) * D_;
        const __nv_bfloat16* pl = qlg + (((size_t)(b * H_ + h)) * L_ + q0) * D_;
        for (int t = tid; t < 128 * 16; t += 256) {
            int r = t >> 4, c = (t & 15) * 8;
            *(uint4*)(sm + AQH + r * 136 + c) = *(const uint4*)(ph + r * 128 + c);
            *(uint4*)(sm + AQL + r * 136 + c) = *(const uint4*)(pl + r * 128 + c);
        }
    }

    float o[16][4];
#pragma unroll
    for (int n = 0; n < 16; n++)
#pragma unroll
        for (int e = 0; e < 4; e++) o[n][e] = 0.f;
    float mrow[2] = {-1e30f, -1e30f};
    float lrow[2] = {0.f, 0.f};

    const int i1 = q0 + wid * 16 + (lane >> 2);
    const int i2 = i1 + 8;

    int t_lo = (q0 - WIN_) >> 6; if (t_lo < 0) t_lo = 0;
    int t_hi = (q0 + 127 + WIN_) >> 6; if (t_hi > L_ / 64 - 1) t_hi = L_ / 64 - 1;

    load_kv(0, t_lo);
    CP_COMMIT();

    for (int tk = t_lo; tk <= t_hi; tk++) {
        const int st = (tk - t_lo) & 1;
        const int j0 = tk * 64;

        CP_WAIT(0);
        __syncthreads();
        if (tk < t_hi) { load_kv(st ^ 1, tk + 1); }
        CP_COMMIT();

        const uint32_t kvb  = smb + (AKV0 + st * AKVSTR) * 2;
        const uint32_t kh_b = kvb;
        const uint32_t kl_b = kvb + 8704 * 2;
        const uint32_t vh_b = kvb + 17408 * 2;
        const uint32_t vl_b = kvb + 26624 * 2;

        // ---- S = Qh*Kh + Ql*Kh + Qh*Kl ----
        float s[8][4];
#pragma unroll
        for (int n = 0; n < 8; n++)
#pragma unroll
            for (int e = 0; e < 4; e++) s[n][e] = 0.f;

#pragma unroll
        for (int pass = 0; pass < 3; pass++) {
            const uint32_t ab = (pass == 1) ? ql_b : qh_b;
            const uint32_t bb = (pass == 2) ? kl_b : kh_b;
#pragma unroll
            for (int k8 = 0; k8 < 8; k8++) {
                uint32_t a0, a1, a2, a3;
                uint32_t aaddr = ab + ((wid * 16 + (lane & 15)) * 136
                                       + k8 * 16 + ((lane >> 4) * 8)) * 2;
                LDSM_X4(a0, a1, a2, a3, aaddr);
#pragma unroll
                for (int n2 = 0; n2 < 4; n2++) {
                    uint32_t b0, b1, b2, b3;
                    uint32_t baddr = bb + ((n2 * 16 + (lane & 15)) * 136
                                           + k8 * 16 + ((lane >> 4) * 8)) * 2;
                    LDSM_X4(b0, b1, b2, b3, baddr);
                    MMA16816(s[2 * n2],     a0, a1, a2, a3, b0, b2);
                    MMA16816(s[2 * n2 + 1], a0, a1, a2, a3, b1, b3);
                }
            }
        }

        // ---- mask + scale ----
#pragma unroll
        for (int n = 0; n < 8; n++) {
            const int jc = j0 + n * 8 + (lane & 3) * 2;
#pragma unroll
            for (int e = 0; e < 4; e++) {
                const int i = (e < 2) ? i1 : i2;
                const int j = jc + (e & 1);
                const bool valid = (unsigned)(i - j + WIN_) <= (unsigned)(2 * WIN_);
                s[n][e] = valid ? s[n][e] * scale : -1e30f;
            }
        }

        // ---- online softmax ----
        float m1 = -1e30f, m2 = -1e30f;
#pragma unroll
        for (int n = 0; n < 8; n++) {
            m1 = fmaxf(m1, fmaxf(s[n][0], s[n][1]));
            m2 = fmaxf(m2, fmaxf(s[n][2], s[n][3]));
        }
        m1 = fmaxf(m1, __shfl_xor_sync(0xffffffffu, m1, 1));
        m1 = fmaxf(m1, __shfl_xor_sync(0xffffffffu, m1, 2));
        m2 = fmaxf(m2, __shfl_xor_sync(0xffffffffu, m2, 1));
        m2 = fmaxf(m2, __shfl_xor_sync(0xffffffffu, m2, 2));
        const float mn1 = fmaxf(mrow[0], m1);
        const float mn2 = fmaxf(mrow[1], m2);
        const float al1 = __expf(mrow[0] - mn1);
        const float al2 = __expf(mrow[1] - mn2);
        float ls1 = 0.f, ls2 = 0.f;
#pragma unroll
        for (int n = 0; n < 8; n++) {
            s[n][0] = __expf(s[n][0] - mn1);
            s[n][1] = __expf(s[n][1] - mn1);
            s[n][2] = __expf(s[n][2] - mn2);
            s[n][3] = __expf(s[n][3] - mn2);
            ls1 += s[n][0] + s[n][1];
            ls2 += s[n][2] + s[n][3];
        }
        ls1 += __shfl_xor_sync(0xffffffffu, ls1, 1);
        ls1 += __shfl_xor_sync(0xffffffffu, ls1, 2);
        ls2 += __shfl_xor_sync(0xffffffffu, ls2, 1);
        ls2 += __shfl_xor_sync(0xffffffffu, ls2, 2);
        lrow[0] = al1 * lrow[0] + ls1;
        lrow[1] = al2 * lrow[1] + ls2;
        mrow[0] = mn1;
        mrow[1] = mn2;
#pragma unroll
        for (int n = 0; n < 16; n++) {
            o[n][0] *= al1; o[n][1] *= al1;
            o[n][2] *= al2; o[n][3] *= al2;
        }

        // ---- O += Ph*Vh + Pl*Vh + Ph*Vl ----
#pragma unroll
        for (int kk = 0; kk < 4; kk++) {
            const int t0 = 2 * kk, t1 = 2 * kk + 1;
            uint32_t ah[4], al[4];
            ah[0] = pkhi(s[t0][0], s[t0][1]); ah[1] = pkhi(s[t0][2], s[t0][3]);
            ah[2] = pkhi(s[t1][0], s[t1][1]); ah[3] = pkhi(s[t1][2], s[t1][3]);
            al[0] = pklo(s[t0][0], s[t0][1]); al[1] = pklo(s[t0][2], s[t0][3]);
            al[2] = pklo(s[t1][0], s[t1][1]); al[3] = pklo(s[t1][2], s[t1][3]);
#pragma unroll
            for (int n2 = 0; n2 < 8; n2++) {
                uint32_t h0, h1, h2, h3, l0, l1, l2, l3;
                uint32_t va = ((n2 * 16 + (lane & 15)) * 72
                               + kk * 16 + ((lane >> 4) * 8)) * 2;
                LDSM_X4(h0, h1, h2, h3, vh_b + va);
                LDSM_X4(l0, l1, l2, l3, vl_b + va);
                MMA16816(o[2 * n2], ah[0], ah[1], ah[2], ah[3], h0, h2);
                MMA16816(o[2 * n2], al[0], al[1], al[2], al[3], h0, h2);
                MMA16816(o[2 * n2], ah[0], ah[1], ah[2], ah[3], l0, l2);
                MMA16816(o[2 * n2 + 1], ah[0], ah[1], ah[2], ah[3], h1, h3);
                MMA16816(o[2 * n2 + 1], al[0], al[1], al[2], al[3], h1, h3);
                MMA16816(o[2 * n2 + 1], ah[0], ah[1], ah[2], ah[3], l1, l3);
            }
        }
    }

    // ---- epilogue ----
    const float inv1 = 1.0f / lrow[0];
    const float inv2 = 1.0f / lrow[1];
    const size_t m1r = (size_t)b * L_ + i1;
    const size_t m2r = (size_t)b * L_ + i2;
#pragma unroll
    for (int n = 0; n < 16; n++) {
        const int col = h * 128 + n * 8 + (lane & 3) * 2;
        {
            float v0 = o[n][0] * inv1, v1 = o[n][1] * inv1;
            __nv_bfloat16 h0 = __float2bfloat16_rn(v0), h1v = __float2bfloat16_rn(v1);
            __nv_bfloat162 hp = {h0, h1v};
            __nv_bfloat162 lp = {__float2bfloat16_rn(v0 - __bfloat162float(h0)),
                                 __float2bfloat16_rn(v1 - __bfloat162float(h1v))};
            *(__nv_bfloat162*)(ao3 + m1r * K3 + col)         = hp;
            *(__nv_bfloat162*)(ao3 + m1r * K3 + HID + col)   = lp;
            *(__nv_bfloat162*)(ao3 + m1r * K3 + 2*HID + col) = hp;
        }
        {
            float v0 = o[n][2] * inv2, v1 = o[n][3] * inv2;
            __nv_bfloat16 h0 = __float2bfloat16_rn(v0), h1v = __float2bfloat16_rn(v1);
            __nv_bfloat162 hp = {h0, h1v};
            __nv_bfloat162 lp = {__float2bfloat16_rn(v0 - __bfloat162float(h0)),
                                 __float2bfloat16_rn(v1 - __bfloat162float(h1v))};
            *(__nv_bfloat162*)(ao3 + m2r * K3 + col)         = hp;
            *(__nv_bfloat162*)(ao3 + m2r * K3 + HID + col)   = lp;
            *(__nv_bfloat162*)(ao3 + m2r * K3 + 2*HID + col) = hp;
        }
    }
}

// ---------------- launch ----------------
extern "C" void kernel_launch(void* const* d_in, const int* in_sizes, int n_in,
                              void* d_out, int out_size)
{
    const float* x    = (const float*)d_in[0];
    const float* cosT = (const float*)d_in[1];
    const float* sinT = (const float*)d_in[2];
    const float* Wq   = (const float*)d_in[3];
    const float* Wk   = (const float*)d_in[4];
    const float* Wv   = (const float*)d_in[5];
    const float* Wo   = (const float*)d_in[6];
    const float* qw   = (const float*)d_in[7];
    const float* kw   = (const float*)d_in[8];
    float* out = (float*)d_out;

    __nv_bfloat16 *x3, *wqkv3, *wo3, *ao3, *qh, *ql, *kh, *kl, *vth, *vtl;
    float *qkvbuf;
    cudaGetSymbolAddress((void**)&x3,     g_x3);
    cudaGetSymbolAddress((void**)&wqkv3,  g_wqkv3);
    cudaGetSymbolAddress((void**)&wo3,    g_wo3);
    cudaGetSymbolAddress((void**)&ao3,    g_ao3);
    cudaGetSymbolAddress((void**)&qkvbuf, g_qkvbuf);
    cudaGetSymbolAddress((void**)&qh,     g_qh);
    cudaGetSymbolAddress((void**)&ql,     g_ql);
    cudaGetSymbolAddress((void**)&kh,     g_kh);
    cudaGetSymbolAddress((void**)&kl,     g_kl);
    cudaGetSymbolAddress((void**)&vth,    g_vth);
    cudaGetSymbolAddress((void**)&vtl,    g_vtl);

    // split-bf16 conversions
    {
        int tot = M_ * HID;
        convert_split<<<tot / 1024, 256>>>(x, x3, HID, tot, 0);
        tot = HID * HID;
        convert_split<<<tot / 1024, 256>>>(Wq, wqkv3, HID, tot, 1);
        tot = KV_ * D_ * HID;
        convert_split<<<tot / 1024, 256>>>(Wk, wqkv3 + (size_t)HID * K3, HID, tot, 1);
        convert_split<<<tot / 1024, 256>>>(Wv, wqkv3 + (size_t)(HID + KV_ * D_) * K3, HID, tot, 1);
        tot = HID * HID;
        convert_split<<<tot / 1024, 256>>>(Wo, wo3, HID, tot, 1);
    }

    cudaFuncSetAttribute(gemm_mma_nt,
                         cudaFuncAttributeMaxDynamicSharedMemorySize, GSMEM_BYTES);

    // fused QKV projection
    gemm_mma_nt<<<dim3(NQKV / 128, M_ / 128), 256, GSMEM_BYTES>>>(
        x3, wqkv3, qkvbuf, M_, NQKV, K3);

    // RMSNorm + RoPE + split outputs
    norm_rope_split<<<dim3(L_, B_, H_ + 2 * KV_), 128>>>(
        qkvbuf, cosT, sinT, qw, kw, qh, ql, kh, kl, vth, vtl);

    // tensor-core banded flash attention
    cudaFuncSetAttribute(attn_mma_kernel,
                         cudaFuncAttributeMaxDynamicSharedMemorySize, ATTN_SMEM_BYTES);
    attn_mma_kernel<<<dim3(L_ / 128, B_ * H_), 256, ATTN_SMEM_BYTES>>>(
        qh, ql, kh, kl, vth, vtl, ao3);

    // output projection
    gemm_mma_nt<<<dim3(HID / 128, M_ / 128), 256, GSMEM_BYTES>>>(
        ao3, wo3, out, M_, HID, K3);
}

// round 11
// speedup vs baseline: 3.1614x; 1.1033x over previous
#include <cuda_runtime.h>
#include <cuda_bf16.h>
#include <math.h>
#include <stdint.h>

#define H_   16
#define KV_  4
#define D_   128
#define B_   2
#define L_   2048
#define HID  2048
#define M_   (B_*L_)
#define WIN_ 512
#define NQKV 3072
#define KK   2048

// ---------------- scratch ----------------
__device__ __align__(16) __nv_bfloat16 g_xh   [(size_t)M_  * KK];
__device__ __align__(16) __nv_bfloat16 g_xl   [(size_t)M_  * KK];
__device__ __align__(16) __nv_bfloat16 g_wqkvh[(size_t)NQKV * KK];
__device__ __align__(16) __nv_bfloat16 g_wqkvl[(size_t)NQKV * KK];
__device__ __align__(16) __nv_bfloat16 g_woh  [(size_t)HID * KK];
__device__ __align__(16) __nv_bfloat16 g_wol  [(size_t)HID * KK];
__device__ __align__(16) __nv_bfloat16 g_aoh  [(size_t)M_  * KK];
__device__ __align__(16) __nv_bfloat16 g_aol  [(size_t)M_  * KK];
__device__ __align__(16) float g_qkvbuf[(size_t)M_ * NQKV];
__device__ __align__(16) __nv_bfloat16 g_qh [(size_t)B_*H_*L_*D_];
__device__ __align__(16) __nv_bfloat16 g_ql [(size_t)B_*H_*L_*D_];
__device__ __align__(16) __nv_bfloat16 g_kh [(size_t)B_*KV_*L_*D_];
__device__ __align__(16) __nv_bfloat16 g_kl [(size_t)B_*KV_*L_*D_];
__device__ __align__(16) __nv_bfloat16 g_vth[(size_t)B_*KV_*D_*L_];
__device__ __align__(16) __nv_bfloat16 g_vtl[(size_t)B_*KV_*D_*L_];

#define CP_ASYNC16(dst, src) \
    asm volatile("cp.async.cg.shared.global [%0], [%1], 16;" :: "r"(dst), "l"(src))
#define CP_COMMIT() asm volatile("cp.async.commit_group;")
#define CP_WAIT(n)  asm volatile("cp.async.wait_group %0;" :: "n"(n))

#define LDSM_X4(r0,r1,r2,r3,addr) \
    asm volatile("ldmatrix.sync.aligned.m8n8.x4.shared.b16 {%0,%1,%2,%3}, [%4];" \
        : "=r"(r0),"=r"(r1),"=r"(r2),"=r"(r3) : "r"(addr))
#define LDSM_X2(r0,r1,addr) \
    asm volatile("ldmatrix.sync.aligned.m8n8.x2.shared.b16 {%0,%1}, [%2];" \
        : "=r"(r0),"=r"(r1) : "r"(addr))
#define MMA16816(c,a0,a1,a2,a3,b0,b1) \
    asm volatile("mma.sync.aligned.m16n8k16.row.col.f32.bf16.bf16.f32 " \
        "{%0,%1,%2,%3},{%4,%5,%6,%7},{%8,%9},{%0,%1,%2,%3};" \
        : "+f"((c)[0]),"+f"((c)[1]),"+f"((c)[2]),"+f"((c)[3]) \
        : "r"(a0),"r"(a1),"r"(a2),"r"(a3),"r"(b0),"r"(b1))

// ---------------- fp32 -> hi/lo bf16 planes ----------------
__global__ __launch_bounds__(256) void convert_hl(
    const float* __restrict__ src,
    __nv_bfloat16* __restrict__ dh, __nv_bfloat16* __restrict__ dl, int total)
{
    int i = (blockIdx.x * 256 + threadIdx.x) * 4;
    if (i >= total) return;
    float4 v = *(const float4*)(src + i);
    float f[4] = {v.x, v.y, v.z, v.w};
    __nv_bfloat16 hi[4], lo[4];
#pragma unroll
    for (int e = 0; e < 4; e++) {
        hi[e] = __float2bfloat16_rn(f[e]);
        lo[e] = __float2bfloat16_rn(f[e] - __bfloat162float(hi[e]));
    }
    __nv_bfloat162 hp0 = {hi[0], hi[1]}, hp1 = {hi[2], hi[3]};
    __nv_bfloat162 lp0 = {lo[0], lo[1]}, lp1 = {lo[2], lo[3]};
    ((__nv_bfloat162*)(dh + i))[0] = hp0; ((__nv_bfloat162*)(dh + i))[1] = hp1;
    ((__nv_bfloat162*)(dl + i))[0] = lp0; ((__nv_bfloat162*)(dl + i))[1] = lp1;
}

// ---------------- 3-pass split-bf16 GEMM: C = (Ah+Al)(Bh+Bl)^T approx ----------------
// 128x128 tile, BK=32, 2-stage cp.async, 256 threads (2x4 warps).
// C[m,n] = sum_k ah*bh + al*bh + ah*bl
#define MAT_B 10240                   // one 128x40-elem tile, bytes
#define ST_B  (4 * MAT_B)             // Ah|Al|Bh|Bl per stage
#define GSM2  (2 * ST_B)              // 81920

__global__ __launch_bounds__(256, 2) void gemm_hl(
    const __nv_bfloat16* __restrict__ Ah, const __nv_bfloat16* __restrict__ Al,
    const __nv_bfloat16* __restrict__ Bh, const __nv_bfloat16* __restrict__ Bl,
    float* __restrict__ C, int M, int N, int K)
{
    extern __shared__ __nv_bfloat16 gsm[];
    const uint32_t smb = (uint32_t)__cvta_generic_to_shared(gsm);

    const int tid  = threadIdx.x;
    const int m0   = blockIdx.y * 128;
    const int n0   = blockIdx.x * 128;
    const int wid  = tid >> 5;
    const int lane = tid & 31;
    const int wm   = wid & 1;
    const int wn   = wid >> 1;

    float acc[4][4][4];
#pragma unroll
    for (int i = 0; i < 4; i++)
#pragma unroll
        for (int j = 0; j < 4; j++)
#pragma unroll
            for (int r = 0; r < 4; r++) acc[i][j][r] = 0.f;

    auto load_stage = [&](int st, int kt) {
        const int k0 = kt * 32;
        const uint32_t base = smb + st * ST_B;
#pragma unroll
        for (int it = 0; it < 2; it++) {
            int idx = tid + it * 256;          // 512 chunks per matrix
            int r = idx >> 2, c = idx & 3;
            uint32_t so = (uint32_t)(r * 80 + c * 16);
            const size_t goA = (size_t)(m0 + r) * K + k0 + c * 8;
            const size_t goB = (size_t)(n0 + r) * K + k0 + c * 8;
            CP_ASYNC16(base + so,             Ah + goA);
            CP_ASYNC16(base + MAT_B + so,     Al + goA);
            CP_ASYNC16(base + 2 * MAT_B + so, Bh + goB);
            CP_ASYNC16(base + 3 * MAT_B + so, Bl + goB);
        }
    };

    const int KT = K / 32;
    load_stage(0, 0);
    CP_COMMIT();

    for (int kt = 0; kt < KT; kt++) {
        CP_WAIT(0);
        __syncthreads();
        if (kt + 1 < KT) load_stage((kt + 1) & 1, kt + 1);
        CP_COMMIT();

        const uint32_t sb = smb + (kt & 1) * ST_B;

#pragma unroll
        for (int ks = 0; ks < 2; ks++) {
            uint32_t ah[4][4], al4[4][4];
#pragma unroll
            for (int mi = 0; mi < 4; mi++) {
                int row = wm * 64 + mi * 16 + (lane & 15);
                uint32_t addr = sb + row * 80 + ks * 32 + ((lane >> 4) << 4);
                LDSM_X4(ah[mi][0], ah[mi][1], ah[mi][2], ah[mi][3], addr);
                LDSM_X4(al4[mi][0], al4[mi][1], al4[mi][2], al4[mi][3], addr + MAT_B);
            }
#pragma unroll
            for (int nh = 0; nh < 2; nh++) {
                uint32_t bh2[2][2], bl2[2][2];
#pragma unroll
                for (int nj = 0; nj < 2; nj++) {
                    int ni = nh * 2 + nj;
                    int row = wn * 32 + ni * 8 + (lane & 7);
                    uint32_t addr = sb + 2 * MAT_B + row * 80 + ks * 32
                                    + (((lane >> 3) & 1) << 4);
                    LDSM_X2(bh2[nj][0], bh2[nj][1], addr);
                    LDSM_X2(bl2[nj][0], bl2[nj][1], addr + MAT_B);
                }
#pragma unroll
                for (int mi = 0; mi < 4; mi++)
#pragma unroll
                    for (int nj = 0; nj < 2; nj++) {
                        float* c = acc[mi][nh * 2 + nj];
                        MMA16816(c, ah[mi][0], ah[mi][1], ah[mi][2], ah[mi][3],
                                 bh2[nj][0], bh2[nj][1]);
                        MMA16816(c, al4[mi][0], al4[mi][1], al4[mi][2], al4[mi][3],
                                 bh2[nj][0], bh2[nj][1]);
                        MMA16816(c, ah[mi][0], ah[mi][1], ah[mi][2], ah[mi][3],
                                 bl2[nj][0], bl2[nj][1]);
                    }
            }
        }
    }

    const int tr = lane >> 2;
    const int tc = (lane & 3) * 2;
#pragma unroll
    for (int mi = 0; mi < 4; mi++)
#pragma unroll
        for (int ni = 0; ni < 4; ni++) {
            int row = m0 + wm * 64 + mi * 16 + tr;
            int col = n0 + wn * 32 + ni * 8 + tc;
            *(float2*)(C + (size_t)row * N + col) =
                make_float2(acc[mi][ni][0], acc[mi][ni][1]);
            *(float2*)(C + (size_t)(row + 8) * N + col) =
                make_float2(acc[mi][ni][2], acc[mi][ni][3]);
        }
}

// ---------------- QK RMSNorm + RoPE + split outputs (+ V split/transpose) ----------------
__global__ __launch_bounds__(128) void norm_rope_split(
    const float* __restrict__ qkv,
    const float* __restrict__ cosT, const float* __restrict__ sinT,
    const float* __restrict__ qw,   const float* __restrict__ kw,
    __nv_bfloat16* __restrict__ qh, __nv_bfloat16* __restrict__ ql,
    __nv_bfloat16* __restrict__ kh, __nv_bfloat16* __restrict__ kl,
    __nv_bfloat16* __restrict__ vth, __nv_bfloat16* __restrict__ vtl)
{
    const int l  = blockIdx.x;
    const int b  = blockIdx.y;
    const int hh = blockIdx.z;
    const int d  = threadIdx.x;
    const size_t m = (size_t)b * L_ + l;

    if (hh >= H_ + KV_) {
        const int kv = hh - (H_ + KV_);
        float x = qkv[m * NQKV + HID + KV_ * D_ + kv * D_ + d];
        __nv_bfloat16 hi = __float2bfloat16_rn(x);
        __nv_bfloat16 lo = __float2bfloat16_rn(x - __bfloat162float(hi));
        size_t idx = ((size_t)(b * KV_ + kv) * D_ + d) * L_ + l;
        vth[idx] = hi; vtl[idx] = lo;
        return;
    }

    float x;
    if (hh < H_) x = qkv[m * NQKV + hh * D_ + d];
    else         x = qkv[m * NQKV + HID + (hh - H_) * D_ + d];

    __shared__ float red[4];
    __shared__ float xn[128];

    float v = x * x;
#pragma unroll
    for (int o = 16; o > 0; o >>= 1) v += __shfl_xor_sync(0xffffffffu, v, o);
    if ((d & 31) == 0) red[d >> 5] = v;
    __syncthreads();
    float total = red[0] + red[1] + red[2] + red[3];
    float rms = rsqrtf(total * (1.0f / 128.0f) + 1e-6f);
    float w = (hh < H_) ? qw[d] : kw[d];
    float xv = x * rms * w;
    xn[d] = xv;
    __syncthreads();

    float c = cosT[l * D_ + d];
    float s = sinT[l * D_ + d];
    float rot = (d < 64) ? -xn[d + 64] : xn[d - 64];
    float out = xv * c + rot * s;

    __nv_bfloat16 hi = __float2bfloat16_rn(out);
    __nv_bfloat16 lo = __float2bfloat16_rn(out - __bfloat162float(hi));
    if (hh < H_) {
        size_t idx = (((size_t)(b * H_ + hh)) * L_ + l) * D_ + d;
        qh[idx] = hi; ql[idx] = lo;
    } else {
        size_t idx = (((size_t)(b * KV_ + (hh - H_))) * L_ + l) * D_ + d;
        kh[idx] = hi; kl[idx] = lo;
    }
}

// ---------------- tensor-core banded flash attention, double-buffered KV ----------------
#define AQH 0
#define AQL 17408
#define AKV0 34816
#define AKVSTR 35840
#define ATTN_SMEM_ELEMS (AKV0 + 2 * AKVSTR)
#define ATTN_SMEM_BYTES (ATTN_SMEM_ELEMS * 2)

__device__ __forceinline__ uint32_t pkhi(float x, float y) {
    __nv_bfloat162 t = __floats2bfloat162_rn(x, y);
    return *reinterpret_cast<uint32_t*>(&t);
}
__device__ __forceinline__ uint32_t pklo(float x, float y) {
    __nv_bfloat16 hx = __float2bfloat16_rn(x), hy = __float2bfloat16_rn(y);
    __nv_bfloat162 t = __floats2bfloat162_rn(x - __bfloat162float(hx),
                                             y - __bfloat162float(hy));
    return *reinterpret_cast<uint32_t*>(&t);
}

__global__ __launch_bounds__(256) void attn_mma_kernel(
    const __nv_bfloat16* __restrict__ qhg, const __nv_bfloat16* __restrict__ qlg,
    const __nv_bfloat16* __restrict__ khg, const __nv_bfloat16* __restrict__ klg,
    const __nv_bfloat16* __restrict__ vhg, const __nv_bfloat16* __restrict__ vlg,
    __nv_bfloat16* __restrict__ aoh, __nv_bfloat16* __restrict__ aol)
{
    extern __shared__ __nv_bfloat16 sm[];

    const int tid  = threadIdx.x;
    const int wid  = tid >> 5;
    const int lane = tid & 31;
    const int qb   = blockIdx.x;
    const int bh   = blockIdx.y;
    const int b    = bh >> 4;
    const int h    = bh & 15;
    const int kv   = h >> 2;
    const int q0   = qb * 128;
    const float scale = 0.08838834764831845f;

    const uint32_t smb  = (uint32_t)__cvta_generic_to_shared(sm);
    const uint32_t qh_b = smb + AQH * 2;
    const uint32_t ql_b = smb + AQL * 2;

    const __nv_bfloat16* kh_src = khg + ((size_t)(b * KV_ + kv)) * L_ * D_;
    const __nv_bfloat16* kl_src = klg + ((size_t)(b * KV_ + kv)) * L_ * D_;
    const __nv_bfloat16* vh_src = vhg + ((size_t)(b * KV_ + kv) * D_) * L_;
    const __nv_bfloat16* vl_src = vlg + ((size_t)(b * KV_ + kv) * D_) * L_;

    auto load_kv = [&](int st, int tk) {
        const int j0 = tk * 64;
        const uint32_t kvb  = smb + (AKV0 + st * AKVSTR) * 2;
        const uint32_t khb  = kvb;
        const uint32_t klb  = kvb + 8704 * 2;
        const uint32_t vhb  = kvb + 17408 * 2;
        const uint32_t vlb  = kvb + 26624 * 2;
#pragma unroll
        for (int t = tid; t < 64 * 16; t += 256) {
            int r = t >> 4, c = (t & 15) * 8;
            uint32_t so = (r * 136 + c) * 2;
            size_t go = (size_t)(j0 + r) * D_ + c;
            CP_ASYNC16(khb + so, kh_src + go);
            CP_ASYNC16(klb + so, kl_src + go);
        }
#pragma unroll
        for (int t = tid; t < 128 * 8; t += 256) {
            int d = t >> 3, c = (t & 7) * 8;
            uint32_t so = (d * 72 + c) * 2;
            size_t go = (size_t)d * L_ + j0 + c;
            CP_ASYNC16(vhb + so, vh_src + go);
            CP_ASYNC16(vlb + so, vl_src + go);
        }
    };

    {
        const __nv_bfloat16* ph = qhg + (((size_t)(b * H_ + h)) * L_ + q0) * D_;
        const __nv_bfloat16* pl = qlg + (((size_t)(b * H_ + h)) * L_ + q0) * D_;
        for (int t = tid; t < 128 * 16; t += 256) {
            int r = t >> 4, c = (t & 15) * 8;
            *(uint4*)(sm + AQH + r * 136 + c) = *(const uint4*)(ph + r * 128 + c);
            *(uint4*)(sm + AQL + r * 136 + c) = *(const uint4*)(pl + r * 128 + c);
        }
    }

    float o[16][4];
#pragma unroll
    for (int n = 0; n < 16; n++)
#pragma unroll
        for (int e = 0; e < 4; e++) o[n][e] = 0.f;
    float mrow[2] = {-1e30f, -1e30f};
    float lrow[2] = {0.f, 0.f};

    const int i1 = q0 + wid * 16 + (lane >> 2);
    const int i2 = i1 + 8;

    int t_lo = (q0 - WIN_) >> 6; if (t_lo < 0) t_lo = 0;
    int t_hi = (q0 + 127 + WIN_) >> 6; if (t_hi > L_ / 64 - 1) t_hi = L_ / 64 - 1;

    load_kv(0, t_lo);
    CP_COMMIT();

    for (int tk = t_lo; tk <= t_hi; tk++) {
        const int st = (tk - t_lo) & 1;
        const int j0 = tk * 64;

        CP_WAIT(0);
        __syncthreads();
        if (tk < t_hi) { load_kv(st ^ 1, tk + 1); }
        CP_COMMIT();

        const uint32_t kvb  = smb + (AKV0 + st * AKVSTR) * 2;
        const uint32_t kh_b = kvb;
        const uint32_t kl_b = kvb + 8704 * 2;
        const uint32_t vh_b = kvb + 17408 * 2;
        const uint32_t vl_b = kvb + 26624 * 2;

        float s[8][4];
#pragma unroll
        for (int n = 0; n < 8; n++)
#pragma unroll
            for (int e = 0; e < 4; e++) s[n][e] = 0.f;

#pragma unroll
        for (int pass = 0; pass < 3; pass++) {
            const uint32_t ab = (pass == 1) ? ql_b : qh_b;
            const uint32_t bb = (pass == 2) ? kl_b : kh_b;
#pragma unroll
            for (int k8 = 0; k8 < 8; k8++) {
                uint32_t a0, a1, a2, a3;
                uint32_t aaddr = ab + ((wid * 16 + (lane & 15)) * 136
                                       + k8 * 16 + ((lane >> 4) * 8)) * 2;
                LDSM_X4(a0, a1, a2, a3, aaddr);
#pragma unroll
                for (int n2 = 0; n2 < 4; n2++) {
                    uint32_t b0, b1, b2, b3;
                    uint32_t baddr = bb + ((n2 * 16 + (lane & 15)) * 136
                                           + k8 * 16 + ((lane >> 4) * 8)) * 2;
                    LDSM_X4(b0, b1, b2, b3, baddr);
                    MMA16816(s[2 * n2],     a0, a1, a2, a3, b0, b2);
                    MMA16816(s[2 * n2 + 1], a0, a1, a2, a3, b1, b3);
                }
            }
        }

#pragma unroll
        for (int n = 0; n < 8; n++) {
            const int jc = j0 + n * 8 + (lane & 3) * 2;
#pragma unroll
            for (int e = 0; e < 4; e++) {
                const int i = (e < 2) ? i1 : i2;
                const int j = jc + (e & 1);
                const bool valid = (unsigned)(i - j + WIN_) <= (unsigned)(2 * WIN_);
                s[n][e] = valid ? s[n][e] * scale : -1e30f;
            }
        }

        float m1 = -1e30f, m2 = -1e30f;
#pragma unroll
        for (int n = 0; n < 8; n++) {
            m1 = fmaxf(m1, fmaxf(s[n][0], s[n][1]));
            m2 = fmaxf(m2, fmaxf(s[n][2], s[n][3]));
        }
        m1 = fmaxf(m1, __shfl_xor_sync(0xffffffffu, m1, 1));
        m1 = fmaxf(m1, __shfl_xor_sync(0xffffffffu, m1, 2));
        m2 = fmaxf(m2, __shfl_xor_sync(0xffffffffu, m2, 1));
        m2 = fmaxf(m2, __shfl_xor_sync(0xffffffffu, m2, 2));
        const float mn1 = fmaxf(mrow[0], m1);
        const float mn2 = fmaxf(mrow[1], m2);
        const float al1 = __expf(mrow[0] - mn1);
        const float al2 = __expf(mrow[1] - mn2);
        float ls1 = 0.f, ls2 = 0.f;
#pragma unroll
        for (int n = 0; n < 8; n++) {
            s[n][0] = __expf(s[n][0] - mn1);
            s[n][1] = __expf(s[n][1] - mn1);
            s[n][2] = __expf(s[n][2] - mn2);
            s[n][3] = __expf(s[n][3] - mn2);
            ls1 += s[n][0] + s[n][1];
            ls2 += s[n][2] + s[n][3];
        }
        ls1 += __shfl_xor_sync(0xffffffffu, ls1, 1);
        ls1 += __shfl_xor_sync(0xffffffffu, ls1, 2);
        ls2 += __shfl_xor_sync(0xffffffffu, ls2, 1);
        ls2 += __shfl_xor_sync(0xffffffffu, ls2, 2);
        lrow[0] = al1 * lrow[0] + ls1;
        lrow[1] = al2 * lrow[1] + ls2;
        mrow[0] = mn1;
        mrow[1] = mn2;
#pragma unroll
        for (int n = 0; n < 16; n++) {
            o[n][0] *= al1; o[n][1] *= al1;
            o[n][2] *= al2; o[n][3] *= al2;
        }

#pragma unroll
        for (int kk = 0; kk < 4; kk++) {
            const int t0 = 2 * kk, t1 = 2 * kk + 1;
            uint32_t ah[4], al[4];
            ah[0] = pkhi(s[t0][0], s[t0][1]); ah[1] = pkhi(s[t0][2], s[t0][3]);
            ah[2] = pkhi(s[t1][0], s[t1][1]); ah[3] = pkhi(s[t1][2], s[t1][3]);
            al[0] = pklo(s[t0][0], s[t0][1]); al[1] = pklo(s[t0][2], s[t0][3]);
            al[2] = pklo(s[t1][0], s[t1][1]); al[3] = pklo(s[t1][2], s[t1][3]);
#pragma unroll
            for (int n2 = 0; n2 < 8; n2++) {
                uint32_t h0, h1, h2, h3, l0, l1, l2, l3;
                uint32_t va = ((n2 * 16 + (lane & 15)) * 72
                               + kk * 16 + ((lane >> 4) * 8)) * 2;
                LDSM_X4(h0, h1, h2, h3, vh_b + va);
                LDSM_X4(l0, l1, l2, l3, vl_b + va);
                MMA16816(o[2 * n2], ah[0], ah[1], ah[2], ah[3], h0, h2);
                MMA16816(o[2 * n2], al[0], al[1], al[2], al[3], h0, h2);
                MMA16816(o[2 * n2], ah[0], ah[1], ah[2], ah[3], l0, l2);
                MMA16816(o[2 * n2 + 1], ah[0], ah[1], ah[2], ah[3], h1, h3);
                MMA16816(o[2 * n2 + 1], al[0], al[1], al[2], al[3], h1, h3);
                MMA16816(o[2 * n2 + 1], ah[0], ah[1], ah[2], ah[3], l1, l3);
            }
        }
    }

    // ---- epilogue: /l, write hi/lo planes of attention output ----
    const float inv1 = 1.0f / lrow[0];
    const float inv2 = 1.0f / lrow[1];
    const size_t m1r = (size_t)b * L_ + i1;
    const size_t m2r = (size_t)b * L_ + i2;
#pragma unroll
    for (int n = 0; n < 16; n++) {
        const int col = h * 128 + n * 8 + (lane & 3) * 2;
        {
            float v0 = o[n][0] * inv1, v1 = o[n][1] * inv1;
            __nv_bfloat16 h0 = __float2bfloat16_rn(v0), h1v = __float2bfloat16_rn(v1);
            __nv_bfloat162 hp = {h0, h1v};
            __nv_bfloat162 lp = {__float2bfloat16_rn(v0 - __bfloat162float(h0)),
                                 __float2bfloat16_rn(v1 - __bfloat162float(h1v))};
            *(__nv_bfloat162*)(aoh + m1r * KK + col) = hp;
            *(__nv_bfloat162*)(aol + m1r * KK + col) = lp;
        }
        {
            float v0 = o[n][2] * inv2, v1 = o[n][3] * inv2;
            __nv_bfloat16 h0 = __float2bfloat16_rn(v0), h1v = __float2bfloat16_rn(v1);
            __nv_bfloat162 hp = {h0, h1v};
            __nv_bfloat162 lp = {__float2bfloat16_rn(v0 - __bfloat162float(h0)),
                                 __float2bfloat16_rn(v1 - __bfloat162float(h1v))};
            *(__nv_bfloat162*)(aoh + m2r * KK + col) = hp;
            *(__nv_bfloat162*)(aol + m2r * KK + col) = lp;
        }
    }
}

// ---------------- launch ----------------
extern "C" void kernel_launch(void* const* d_in, const int* in_sizes, int n_in,
                              void* d_out, int out_size)
{
    const float* x    = (const float*)d_in[0];
    const float* cosT = (const float*)d_in[1];
    const float* sinT = (const float*)d_in[2];
    const float* Wq   = (const float*)d_in[3];
    const float* Wk   = (const float*)d_in[4];
    const float* Wv   = (const float*)d_in[5];
    const float* Wo   = (const float*)d_in[6];
    const float* qw   = (const float*)d_in[7];
    const float* kw   = (const float*)d_in[8];
    float* out = (float*)d_out;

    __nv_bfloat16 *xh, *xl, *wqkvh, *wqkvl, *woh, *wol, *aoh, *aol;
    __nv_bfloat16 *qh, *ql, *kh, *kl, *vth, *vtl;
    float *qkvbuf;
    cudaGetSymbolAddress((void**)&xh,     g_xh);
    cudaGetSymbolAddress((void**)&xl,     g_xl);
    cudaGetSymbolAddress((void**)&wqkvh,  g_wqkvh);
    cudaGetSymbolAddress((void**)&wqkvl,  g_wqkvl);
    cudaGetSymbolAddress((void**)&woh,    g_woh);
    cudaGetSymbolAddress((void**)&wol,    g_wol);
    cudaGetSymbolAddress((void**)&aoh,    g_aoh);
    cudaGetSymbolAddress((void**)&aol,    g_aol);
    cudaGetSymbolAddress((void**)&qkvbuf, g_qkvbuf);
    cudaGetSymbolAddress((void**)&qh,     g_qh);
    cudaGetSymbolAddress((void**)&ql,     g_ql);
    cudaGetSymbolAddress((void**)&kh,     g_kh);
    cudaGetSymbolAddress((void**)&kl,     g_kl);
    cudaGetSymbolAddress((void**)&vth,    g_vth);
    cudaGetSymbolAddress((void**)&vtl,    g_vtl);

    // hi/lo conversions
    {
        int tot = M_ * HID;
        convert_hl<<<tot / 1024, 256>>>(x, xh, xl, tot);
        tot = HID * HID;
        convert_hl<<<tot / 1024, 256>>>(Wq, wqkvh, wqkvl, tot);
        tot = KV_ * D_ * HID;
        convert_hl<<<tot / 1024, 256>>>(Wk, wqkvh + (size_t)HID * KK,
                                        wqkvl + (size_t)HID * KK, tot);
        convert_hl<<<tot / 1024, 256>>>(Wv, wqkvh + (size_t)(HID + KV_ * D_) * KK,
                                        wqkvl + (size_t)(HID + KV_ * D_) * KK, tot);
        tot = HID * HID;
        convert_hl<<<tot / 1024, 256>>>(Wo, woh, wol, tot);
    }

    cudaFuncSetAttribute(gemm_hl,
                         cudaFuncAttributeMaxDynamicSharedMemorySize, GSM2);

    // fused QKV projection
    gemm_hl<<<dim3(NQKV / 128, M_ / 128), 256, GSM2>>>(
        xh, xl, wqkvh, wqkvl, qkvbuf, M_, NQKV, KK);

    // RMSNorm + RoPE + split outputs
    norm_rope_split<<<dim3(L_, B_, H_ + 2 * KV_), 128>>>(
        qkvbuf, cosT, sinT, qw, kw, qh, ql, kh, kl, vth, vtl);

    // tensor-core banded flash attention
    cudaFuncSetAttribute(attn_mma_kernel,
                         cudaFuncAttributeMaxDynamicSharedMemorySize, ATTN_SMEM_BYTES);
    attn_mma_kernel<<<dim3(L_ / 128, B_ * H_), 256, ATTN_SMEM_BYTES>>>(
        qh, ql, kh, kl, vth, vtl, aoh, aol);

    // output projection
    gemm_hl<<<dim3(HID / 128, M_ / 128), 256, GSM2>>>(
        aoh, aol, woh, wol, out, M_, HID, KK);
}